// round 9
// baseline (speedup 1.0000x reference)
#include <cuda_runtime.h>

#define D_ 512
#define S_ 2048
#define B_ 4
#define M_ (B_*S_)

// ---- scratch (device globals; no allocation allowed) ----
__device__ __align__(16) float g_Qre[M_*D_], g_Qim[M_*D_];
__device__ __align__(16) float g_Kre[M_*D_], g_Kim[M_*D_];
__device__ __align__(16) float g_Vre[M_*D_], g_Vim[M_*D_];
__device__ __align__(16) float g_S[(size_t)B_*S_*S_];

#define BM 64
#define BN 64
#define BK 16
#define LDS_PAD 68

static __device__ __forceinline__ void cfma4(float4& cre, float4& cim,
                                             float ar, float ai,
                                             const float4& wr, const float4& wi) {
    cre.x = fmaf(ar, wr.x, cre.x); cre.x = fmaf(-ai, wi.x, cre.x);
    cre.y = fmaf(ar, wr.y, cre.y); cre.y = fmaf(-ai, wi.y, cre.y);
    cre.z = fmaf(ar, wr.z, cre.z); cre.z = fmaf(-ai, wi.z, cre.z);
    cre.w = fmaf(ar, wr.w, cre.w); cre.w = fmaf(-ai, wi.w, cre.w);
    cim.x = fmaf(ar, wi.x, cim.x); cim.x = fmaf(ai, wr.x, cim.x);
    cim.y = fmaf(ar, wi.y, cim.y); cim.y = fmaf(ai, wr.y, cim.y);
    cim.z = fmaf(ar, wi.z, cim.z); cim.z = fmaf(ai, wr.z, cim.z);
    cim.w = fmaf(ar, wi.w, cim.w); cim.w = fmaf(ai, wr.w, cim.w);
}

static __device__ __forceinline__ void rfma4(float4& acc, float ar, float ai,
                                             const float4& kr, const float4& ki) {
    acc.x = fmaf(ar, kr.x, acc.x); acc.x = fmaf(ai, ki.x, acc.x);
    acc.y = fmaf(ar, kr.y, acc.y); acc.y = fmaf(ai, ki.y, acc.y);
    acc.z = fmaf(ar, kr.z, acc.z); acc.z = fmaf(ai, ki.z, acc.z);
    acc.w = fmaf(ar, kr.w, acc.w); acc.w = fmaf(ai, ki.w, acc.w);
}

static __device__ __forceinline__ void sfma4(float4& cre, float a, const float4& vr) {
    cre.x = fmaf(a, vr.x, cre.x);
    cre.y = fmaf(a, vr.y, cre.y);
    cre.z = fmaf(a, vr.z, cre.z);
    cre.w = fmaf(a, vr.w, cre.w);
}

// =====================================================================
// Complex projection: Y = X @ W^T + b
// =====================================================================
__global__ __launch_bounds__(256) void proj_kernel(
    const float* __restrict__ xre, const float* __restrict__ xim,
    const float* __restrict__ Wre, const float* __restrict__ Wim,
    const float* __restrict__ bre, const float* __restrict__ bim,
    int which)
{
    __shared__ __align__(16) float Asr[BK*LDS_PAD], Asi[BK*LDS_PAD];
    __shared__ __align__(16) float Bsr[BK*LDS_PAD], Bsi[BK*LDS_PAD];

    float* yre = (which == 0) ? g_Qre : (which == 1) ? g_Kre : g_Vre;
    float* yim = (which == 0) ? g_Qim : (which == 1) ? g_Kim : g_Vim;

    const int tid = threadIdx.x;
    const int m0 = blockIdx.y * BM;
    const int n0 = blockIdx.x * BN;
    const int ty = tid >> 4, tx = tid & 15;
    const int lrow = tid >> 2;
    const int lcol = (tid & 3) * 4;

    float4 accre[4], accim[4];
#pragma unroll
    for (int i = 0; i < 4; i++) {
        accre[i] = make_float4(0.f, 0.f, 0.f, 0.f);
        accim[i] = make_float4(0.f, 0.f, 0.f, 0.f);
    }

    for (int k0 = 0; k0 < D_; k0 += BK) {
        float4 a_r = *(const float4*)(xre + (size_t)(m0 + lrow) * D_ + k0 + lcol);
        float4 a_i = *(const float4*)(xim + (size_t)(m0 + lrow) * D_ + k0 + lcol);
        float4 b_r = *(const float4*)(Wre + (size_t)(n0 + lrow) * D_ + k0 + lcol);
        float4 b_i = *(const float4*)(Wim + (size_t)(n0 + lrow) * D_ + k0 + lcol);
        __syncthreads();
        Asr[(lcol+0)*LDS_PAD + lrow] = a_r.x; Asr[(lcol+1)*LDS_PAD + lrow] = a_r.y;
        Asr[(lcol+2)*LDS_PAD + lrow] = a_r.z; Asr[(lcol+3)*LDS_PAD + lrow] = a_r.w;
        Asi[(lcol+0)*LDS_PAD + lrow] = a_i.x; Asi[(lcol+1)*LDS_PAD + lrow] = a_i.y;
        Asi[(lcol+2)*LDS_PAD + lrow] = a_i.z; Asi[(lcol+3)*LDS_PAD + lrow] = a_i.w;
        Bsr[(lcol+0)*LDS_PAD + lrow] = b_r.x; Bsr[(lcol+1)*LDS_PAD + lrow] = b_r.y;
        Bsr[(lcol+2)*LDS_PAD + lrow] = b_r.z; Bsr[(lcol+3)*LDS_PAD + lrow] = b_r.w;
        Bsi[(lcol+0)*LDS_PAD + lrow] = b_i.x; Bsi[(lcol+1)*LDS_PAD + lrow] = b_i.y;
        Bsi[(lcol+2)*LDS_PAD + lrow] = b_i.z; Bsi[(lcol+3)*LDS_PAD + lrow] = b_i.w;
        __syncthreads();
#pragma unroll
        for (int k = 0; k < BK; k++) {
            float4 ar = *(const float4*)&Asr[k*LDS_PAD + ty*4];
            float4 ai = *(const float4*)&Asi[k*LDS_PAD + ty*4];
            float4 wr = *(const float4*)&Bsr[k*LDS_PAD + tx*4];
            float4 wi = *(const float4*)&Bsi[k*LDS_PAD + tx*4];
            cfma4(accre[0], accim[0], ar.x, ai.x, wr, wi);
            cfma4(accre[1], accim[1], ar.y, ai.y, wr, wi);
            cfma4(accre[2], accim[2], ar.z, ai.z, wr, wi);
            cfma4(accre[3], accim[3], ar.w, ai.w, wr, wi);
        }
    }

    const int n = n0 + tx*4;
    const float br0 = bre[n+0], br1 = bre[n+1], br2 = bre[n+2], br3 = bre[n+3];
    const float bi0 = bim[n+0], bi1 = bim[n+1], bi2 = bim[n+2], bi3 = bim[n+3];
#pragma unroll
    for (int i = 0; i < 4; i++) {
        const int m = m0 + ty*4 + i;
        float4 orv = make_float4(accre[i].x + br0, accre[i].y + br1,
                                 accre[i].z + br2, accre[i].w + br3);
        float4 oiv = make_float4(accim[i].x + bi0, accim[i].y + bi1,
                                 accim[i].z + bi2, accim[i].w + bi3);
        *(float4*)(yre + (size_t)m * D_ + n) = orv;
        *(float4*)(yim + (size_t)m * D_ + n) = oiv;
    }
}

// =====================================================================
// Scores: S = Qre Kre^T + Qim Kim^T  (Re(Q K^H)), statics only.
// =====================================================================
__global__ __launch_bounds__(256) void scores_kernel()
{
    __shared__ __align__(16) float Asr[BK*LDS_PAD], Asi[BK*LDS_PAD];
    __shared__ __align__(16) float Bsr[BK*LDS_PAD], Bsi[BK*LDS_PAD];

    const int b = blockIdx.z;
    const float* qre = g_Qre + (size_t)b * S_ * D_;
    const float* qim = g_Qim + (size_t)b * S_ * D_;
    const float* kre = g_Kre + (size_t)b * S_ * D_;
    const float* kim = g_Kim + (size_t)b * S_ * D_;
    float* Sout = g_S + (size_t)b * S_ * S_;

    const int tid = threadIdx.x;
    const int m0 = blockIdx.y * BM;
    const int n0 = blockIdx.x * BN;
    const int ty = tid >> 4, tx = tid & 15;
    const int lrow = tid >> 2;
    const int lcol = (tid & 3) * 4;

    float4 acc[4];
#pragma unroll
    for (int i = 0; i < 4; i++) acc[i] = make_float4(0.f, 0.f, 0.f, 0.f);

    for (int k0 = 0; k0 < D_; k0 += BK) {
        float4 a_r = *(const float4*)(qre + (size_t)(m0 + lrow) * D_ + k0 + lcol);
        float4 a_i = *(const float4*)(qim + (size_t)(m0 + lrow) * D_ + k0 + lcol);
        float4 b_r = *(const float4*)(kre + (size_t)(n0 + lrow) * D_ + k0 + lcol);
        float4 b_i = *(const float4*)(kim + (size_t)(n0 + lrow) * D_ + k0 + lcol);
        __syncthreads();
        Asr[(lcol+0)*LDS_PAD + lrow] = a_r.x; Asr[(lcol+1)*LDS_PAD + lrow] = a_r.y;
        Asr[(lcol+2)*LDS_PAD + lrow] = a_r.z; Asr[(lcol+3)*LDS_PAD + lrow] = a_r.w;
        Asi[(lcol+0)*LDS_PAD + lrow] = a_i.x; Asi[(lcol+1)*LDS_PAD + lrow] = a_i.y;
        Asi[(lcol+2)*LDS_PAD + lrow] = a_i.z; Asi[(lcol+3)*LDS_PAD + lrow] = a_i.w;
        Bsr[(lcol+0)*LDS_PAD + lrow] = b_r.x; Bsr[(lcol+1)*LDS_PAD + lrow] = b_r.y;
        Bsr[(lcol+2)*LDS_PAD + lrow] = b_r.z; Bsr[(lcol+3)*LDS_PAD + lrow] = b_r.w;
        Bsi[(lcol+0)*LDS_PAD + lrow] = b_i.x; Bsi[(lcol+1)*LDS_PAD + lrow] = b_i.y;
        Bsi[(lcol+2)*LDS_PAD + lrow] = b_i.z; Bsi[(lcol+3)*LDS_PAD + lrow] = b_i.w;
        __syncthreads();
#pragma unroll
        for (int k = 0; k < BK; k++) {
            float4 ar = *(const float4*)&Asr[k*LDS_PAD + ty*4];
            float4 ai = *(const float4*)&Asi[k*LDS_PAD + ty*4];
            float4 kr = *(const float4*)&Bsr[k*LDS_PAD + tx*4];
            float4 ki = *(const float4*)&Bsi[k*LDS_PAD + tx*4];
            rfma4(acc[0], ar.x, ai.x, kr, ki);
            rfma4(acc[1], ar.y, ai.y, kr, ki);
            rfma4(acc[2], ar.z, ai.z, kr, ki);
            rfma4(acc[3], ar.w, ai.w, kr, ki);
        }
    }

#pragma unroll
    for (int i = 0; i < 4; i++) {
        const int m = m0 + ty*4 + i;
        *(float4*)(Sout + (size_t)m * S_ + n0 + tx*4) = acc[i];
    }
}

// =====================================================================
// Row softmax over 2048 cols, in place (statics only).
// =====================================================================
__global__ __launch_bounds__(256) void softmax_kernel()
{
    __shared__ float sh[8];
    float* p = g_S + (size_t)blockIdx.x * S_;
    const int t = threadIdx.x;

    float4 v0 = *(float4*)(p + t*4);
    float4 v1 = *(float4*)(p + 1024 + t*4);

    float m = fmaxf(fmaxf(fmaxf(v0.x, v0.y), fmaxf(v0.z, v0.w)),
                    fmaxf(fmaxf(v1.x, v1.y), fmaxf(v1.z, v1.w)));
#pragma unroll
    for (int o = 16; o; o >>= 1) m = fmaxf(m, __shfl_xor_sync(0xffffffffu, m, o));
    if ((t & 31) == 0) sh[t >> 5] = m;
    __syncthreads();
    m = sh[0];
#pragma unroll
    for (int i = 1; i < 8; i++) m = fmaxf(m, sh[i]);
    __syncthreads();

    v0.x = __expf(v0.x - m); v0.y = __expf(v0.y - m);
    v0.z = __expf(v0.z - m); v0.w = __expf(v0.w - m);
    v1.x = __expf(v1.x - m); v1.y = __expf(v1.y - m);
    v1.z = __expf(v1.z - m); v1.w = __expf(v1.w - m);

    float s = (v0.x + v0.y) + (v0.z + v0.w) + (v1.x + v1.y) + (v1.z + v1.w);
#pragma unroll
    for (int o = 16; o; o >>= 1) s += __shfl_xor_sync(0xffffffffu, s, o);
    if ((t & 31) == 0) sh[t >> 5] = s;
    __syncthreads();
    s = (sh[0] + sh[1]) + (sh[2] + sh[3]) + (sh[4] + sh[5]) + (sh[6] + sh[7]);
    const float inv = 1.0f / s;

    v0.x *= inv; v0.y *= inv; v0.z *= inv; v0.w *= inv;
    v1.x *= inv; v1.y *= inv; v1.z *= inv; v1.w *= inv;
    *(float4*)(p + t*4) = v0;
    *(float4*)(p + 1024 + t*4) = v1;
}

// =====================================================================
// AV (REAL PART ONLY): out[b][s][e] = sum_t attn[b][s][t] * Vre[b][t][e]
// Writes exactly out_size = B*S*D float32 values.
// =====================================================================
__global__ __launch_bounds__(256) void av_kernel(float* __restrict__ out)
{
    __shared__ __align__(16) float As[BK*LDS_PAD];
    __shared__ __align__(16) float Bsr[BK*LDS_PAD];

    const int b = blockIdx.z;
    const float* attn = g_S + (size_t)b * S_ * S_;
    const float* vre = g_Vre + (size_t)b * S_ * D_;

    const int tid = threadIdx.x;
    const int m0 = blockIdx.y * BM;
    const int n0 = blockIdx.x * BN;
    const int ty = tid >> 4, tx = tid & 15;
    const int lrow = tid >> 2;
    const int lcol = (tid & 3) * 4;
    const int brow = tid >> 4;
    const int bcol = (tid & 15) * 4;

    float4 accre[4];
#pragma unroll
    for (int i = 0; i < 4; i++) accre[i] = make_float4(0.f, 0.f, 0.f, 0.f);

    for (int k0 = 0; k0 < S_; k0 += BK) {
        float4 a   = *(const float4*)(attn + (size_t)(m0 + lrow) * S_ + k0 + lcol);
        float4 b_r = *(const float4*)(vre + (size_t)(k0 + brow) * D_ + n0 + bcol);
        __syncthreads();
        As[(lcol+0)*LDS_PAD + lrow] = a.x; As[(lcol+1)*LDS_PAD + lrow] = a.y;
        As[(lcol+2)*LDS_PAD + lrow] = a.z; As[(lcol+3)*LDS_PAD + lrow] = a.w;
        *(float4*)&Bsr[brow*LDS_PAD + bcol] = b_r;
        __syncthreads();
#pragma unroll
        for (int k = 0; k < BK; k++) {
            float4 av = *(const float4*)&As[k*LDS_PAD + ty*4];
            float4 vr = *(const float4*)&Bsr[k*LDS_PAD + tx*4];
            sfma4(accre[0], av.x, vr);
            sfma4(accre[1], av.y, vr);
            sfma4(accre[2], av.z, vr);
            sfma4(accre[3], av.w, vr);
        }
    }

#pragma unroll
    for (int i = 0; i < 4; i++) {
        const int m = m0 + ty*4 + i;
        // contiguous 4 floats; max index = B*S*D - 1 (within out_size)
        *(float4*)(out + ((size_t)b * S_ + m) * D_ + n0 + tx*4) = accre[i];
    }
}

// =====================================================================
extern "C" void kernel_launch(void* const* d_in, const int* in_sizes, int n_in,
                              void* d_out, int out_size)
{
    (void)in_sizes; (void)n_in; (void)out_size;

    const float* xre   = (const float*)d_in[0];
    const float* xim   = (const float*)d_in[1];
    const float* Wq_re = (const float*)d_in[2];
    const float* Wq_im = (const float*)d_in[3];
    const float* bq_re = (const float*)d_in[4];
    const float* bq_im = (const float*)d_in[5];
    const float* Wk_re = (const float*)d_in[6];
    const float* Wk_im = (const float*)d_in[7];
    const float* bk_re = (const float*)d_in[8];
    const float* bk_im = (const float*)d_in[9];
    const float* Wv_re = (const float*)d_in[10];
    const float* Wv_im = (const float*)d_in[11];
    const float* bv_re = (const float*)d_in[12];
    const float* bv_im = (const float*)d_in[13];

    dim3 projGrid(D_/BN, M_/BM);
    proj_kernel<<<projGrid, 256>>>(xre, xim, Wq_re, Wq_im, bq_re, bq_im, 0);
    proj_kernel<<<projGrid, 256>>>(xre, xim, Wk_re, Wk_im, bk_re, bk_im, 1);
    proj_kernel<<<projGrid, 256>>>(xre, xim, Wv_re, Wv_im, bv_re, bv_im, 2);

    dim3 scoreGrid(S_/BN, S_/BM, B_);
    scores_kernel<<<scoreGrid, 256>>>();

    softmax_kernel<<<B_*S_, 256>>>();

    dim3 avGrid(D_/BN, S_/BM, B_);
    av_kernel<<<avGrid, 256>>>((float*)d_out);
}

// round 11
// speedup vs baseline: 1.2603x; 1.2603x over previous
#include <cuda_runtime.h>
#include <cuda_bf16.h>
#include <cstdint>

#define D_ 512
#define S_ 2048
#define B_ 4
#define M_ (B_*S_)
#define KC_ 1024   // concat(re,im) contraction length for scores

// ---- scratch (device globals; no allocation allowed) ----
__device__ __align__(16) float g_Qre[M_*D_], g_Qim[M_*D_];
__device__ __align__(16) float g_Kre[M_*D_], g_Kim[M_*D_];
__device__ __align__(16) float g_Vre[M_*D_], g_Vim[M_*D_];
__device__ __align__(16) float g_S[(size_t)B_*S_*S_];
__device__ __align__(16) __nv_bfloat16 g_Qhi[(size_t)M_*KC_], g_Qlo[(size_t)M_*KC_];
__device__ __align__(16) __nv_bfloat16 g_Khi[(size_t)M_*KC_], g_Klo[(size_t)M_*KC_];

// =====================================================================
// mma.sync helpers (baseline PTX, sm_80+; compiles for compute_103)
// =====================================================================
static __device__ __forceinline__ uint32_t smem_u32(const void* p) {
    uint32_t a;
    asm("{ .reg .u64 t; cvta.to.shared.u64 t, %1; cvt.u32.u64 %0, t; }"
        : "=r"(a) : "l"(p));
    return a;
}
static __device__ __forceinline__ void ldsm_x4(uint32_t addr, uint32_t& r0,
                                               uint32_t& r1, uint32_t& r2, uint32_t& r3) {
    asm volatile("ldmatrix.sync.aligned.m8n8.x4.shared.b16 {%0,%1,%2,%3}, [%4];"
                 : "=r"(r0), "=r"(r1), "=r"(r2), "=r"(r3) : "r"(addr));
}
static __device__ __forceinline__ void mma_bf16(float* d, const uint32_t* a,
                                                const uint32_t* b) {
    asm volatile("mma.sync.aligned.m16n8k16.row.col.f32.bf16.bf16.f32 "
                 "{%0,%1,%2,%3}, {%4,%5,%6,%7}, {%8,%9}, {%0,%1,%2,%3};"
                 : "+f"(d[0]), "+f"(d[1]), "+f"(d[2]), "+f"(d[3])
                 : "r"(a[0]), "r"(a[1]), "r"(a[2]), "r"(a[3]),
                   "r"(b[0]), "r"(b[1]));
}

// =====================================================================
// FFMA helpers (proj / AV keep the proven R8 fp32 path)
// =====================================================================
static __device__ __forceinline__ void cfma4(float4& cre, float4& cim,
                                             float ar, float ai,
                                             const float4& wr, const float4& wi) {
    cre.x = fmaf(ar, wr.x, cre.x); cre.x = fmaf(-ai, wi.x, cre.x);
    cre.y = fmaf(ar, wr.y, cre.y); cre.y = fmaf(-ai, wi.y, cre.y);
    cre.z = fmaf(ar, wr.z, cre.z); cre.z = fmaf(-ai, wi.z, cre.z);
    cre.w = fmaf(ar, wr.w, cre.w); cre.w = fmaf(-ai, wi.w, cre.w);
    cim.x = fmaf(ar, wi.x, cim.x); cim.x = fmaf(ai, wr.x, cim.x);
    cim.y = fmaf(ar, wi.y, cim.y); cim.y = fmaf(ai, wr.y, cim.y);
    cim.z = fmaf(ar, wi.z, cim.z); cim.z = fmaf(ai, wr.z, cim.z);
    cim.w = fmaf(ar, wi.w, cim.w); cim.w = fmaf(ai, wr.w, cim.w);
}
static __device__ __forceinline__ void sfma4(float4& cre, float a, const float4& vr) {
    cre.x = fmaf(a, vr.x, cre.x);
    cre.y = fmaf(a, vr.y, cre.y);
    cre.z = fmaf(a, vr.z, cre.z);
    cre.w = fmaf(a, vr.w, cre.w);
}

#define BM 64
#define BN 64
#define BK 16
#define LDS_PAD 68

// =====================================================================
// Complex projection: Y = X @ W^T + b  (fp32 FFMA)
// =====================================================================
__global__ __launch_bounds__(256) void proj_kernel(
    const float* __restrict__ xre, const float* __restrict__ xim,
    const float* __restrict__ Wre, const float* __restrict__ Wim,
    const float* __restrict__ bre, const float* __restrict__ bim,
    int which)
{
    __shared__ __align__(16) float Asr[BK*LDS_PAD], Asi[BK*LDS_PAD];
    __shared__ __align__(16) float Bsr[BK*LDS_PAD], Bsi[BK*LDS_PAD];

    float* yre = (which == 0) ? g_Qre : (which == 1) ? g_Kre : g_Vre;
    float* yim = (which == 0) ? g_Qim : (which == 1) ? g_Kim : g_Vim;

    const int tid = threadIdx.x;
    const int m0 = blockIdx.y * BM;
    const int n0 = blockIdx.x * BN;
    const int ty = tid >> 4, tx = tid & 15;
    const int lrow = tid >> 2;
    const int lcol = (tid & 3) * 4;

    float4 accre[4], accim[4];
#pragma unroll
    for (int i = 0; i < 4; i++) {
        accre[i] = make_float4(0.f, 0.f, 0.f, 0.f);
        accim[i] = make_float4(0.f, 0.f, 0.f, 0.f);
    }

    for (int k0 = 0; k0 < D_; k0 += BK) {
        float4 a_r = *(const float4*)(xre + (size_t)(m0 + lrow) * D_ + k0 + lcol);
        float4 a_i = *(const float4*)(xim + (size_t)(m0 + lrow) * D_ + k0 + lcol);
        float4 b_r = *(const float4*)(Wre + (size_t)(n0 + lrow) * D_ + k0 + lcol);
        float4 b_i = *(const float4*)(Wim + (size_t)(n0 + lrow) * D_ + k0 + lcol);
        __syncthreads();
        Asr[(lcol+0)*LDS_PAD + lrow] = a_r.x; Asr[(lcol+1)*LDS_PAD + lrow] = a_r.y;
        Asr[(lcol+2)*LDS_PAD + lrow] = a_r.z; Asr[(lcol+3)*LDS_PAD + lrow] = a_r.w;
        Asi[(lcol+0)*LDS_PAD + lrow] = a_i.x; Asi[(lcol+1)*LDS_PAD + lrow] = a_i.y;
        Asi[(lcol+2)*LDS_PAD + lrow] = a_i.z; Asi[(lcol+3)*LDS_PAD + lrow] = a_i.w;
        Bsr[(lcol+0)*LDS_PAD + lrow] = b_r.x; Bsr[(lcol+1)*LDS_PAD + lrow] = b_r.y;
        Bsr[(lcol+2)*LDS_PAD + lrow] = b_r.z; Bsr[(lcol+3)*LDS_PAD + lrow] = b_r.w;
        Bsi[(lcol+0)*LDS_PAD + lrow] = b_i.x; Bsi[(lcol+1)*LDS_PAD + lrow] = b_i.y;
        Bsi[(lcol+2)*LDS_PAD + lrow] = b_i.z; Bsi[(lcol+3)*LDS_PAD + lrow] = b_i.w;
        __syncthreads();
#pragma unroll
        for (int k = 0; k < BK; k++) {
            float4 ar = *(const float4*)&Asr[k*LDS_PAD + ty*4];
            float4 ai = *(const float4*)&Asi[k*LDS_PAD + ty*4];
            float4 wr = *(const float4*)&Bsr[k*LDS_PAD + tx*4];
            float4 wi = *(const float4*)&Bsi[k*LDS_PAD + tx*4];
            cfma4(accre[0], accim[0], ar.x, ai.x, wr, wi);
            cfma4(accre[1], accim[1], ar.y, ai.y, wr, wi);
            cfma4(accre[2], accim[2], ar.z, ai.z, wr, wi);
            cfma4(accre[3], accim[3], ar.w, ai.w, wr, wi);
        }
    }

    const int n = n0 + tx*4;
    const float br0 = bre[n+0], br1 = bre[n+1], br2 = bre[n+2], br3 = bre[n+3];
    const float bi0 = bim[n+0], bi1 = bim[n+1], bi2 = bim[n+2], bi3 = bim[n+3];
#pragma unroll
    for (int i = 0; i < 4; i++) {
        const int m = m0 + ty*4 + i;
        float4 orv = make_float4(accre[i].x + br0, accre[i].y + br1,
                                 accre[i].z + br2, accre[i].w + br3);
        float4 oiv = make_float4(accim[i].x + bi0, accim[i].y + bi1,
                                 accim[i].z + bi2, accim[i].w + bi3);
        *(float4*)(yre + (size_t)m * D_ + n) = orv;
        *(float4*)(yim + (size_t)m * D_ + n) = oiv;
    }
}

// =====================================================================
// Split Q/K fp32 -> bf16 hi/lo, layout [M_][KC_] with cols = re||im
// =====================================================================
__global__ __launch_bounds__(256) void split_convert_kernel()
{
    const size_t idx = (size_t)blockIdx.x * blockDim.x + threadIdx.x;
    const size_t row = idx >> 8;
    const int c4 = (int)(idx & 255) * 4;

    const size_t soff = (c4 < D_) ? (row * D_ + c4) : (row * D_ + (c4 - D_));
    const float4 q = (c4 < D_) ? *(const float4*)(g_Qre + soff)
                               : *(const float4*)(g_Qim + soff);
    const float4 k = (c4 < D_) ? *(const float4*)(g_Kre + soff)
                               : *(const float4*)(g_Kim + soff);

    const size_t doff = row * KC_ + c4;

    __nv_bfloat16 qh0 = __float2bfloat16_rn(q.x), qh1 = __float2bfloat16_rn(q.y);
    __nv_bfloat16 qh2 = __float2bfloat16_rn(q.z), qh3 = __float2bfloat16_rn(q.w);
    *(__nv_bfloat162*)(g_Qhi + doff)     = __nv_bfloat162(qh0, qh1);
    *(__nv_bfloat162*)(g_Qhi + doff + 2) = __nv_bfloat162(qh2, qh3);
    *(__nv_bfloat162*)(g_Qlo + doff)     = __nv_bfloat162(
        __float2bfloat16_rn(q.x - __bfloat162float(qh0)),
        __float2bfloat16_rn(q.y - __bfloat162float(qh1)));
    *(__nv_bfloat162*)(g_Qlo + doff + 2) = __nv_bfloat162(
        __float2bfloat16_rn(q.z - __bfloat162float(qh2)),
        __float2bfloat16_rn(q.w - __bfloat162float(qh3)));

    __nv_bfloat16 kh0 = __float2bfloat16_rn(k.x), kh1 = __float2bfloat16_rn(k.y);
    __nv_bfloat16 kh2 = __float2bfloat16_rn(k.z), kh3 = __float2bfloat16_rn(k.w);
    *(__nv_bfloat162*)(g_Khi + doff)     = __nv_bfloat162(kh0, kh1);
    *(__nv_bfloat162*)(g_Khi + doff + 2) = __nv_bfloat162(kh2, kh3);
    *(__nv_bfloat162*)(g_Klo + doff)     = __nv_bfloat162(
        __float2bfloat16_rn(k.x - __bfloat162float(kh0)),
        __float2bfloat16_rn(k.y - __bfloat162float(kh1)));
    *(__nv_bfloat162*)(g_Klo + doff + 2) = __nv_bfloat162(
        __float2bfloat16_rn(k.z - __bfloat162float(kh2)),
        __float2bfloat16_rn(k.w - __bfloat162float(kh3)));
}

// =====================================================================
// Scores via mma.sync bf16: S = Qhi·Khi^T + Qlo·Khi^T + Qhi·Klo^T
// CTA tile 128x128, BK=32, 8 warps (warp tile 32x64), double-buffered.
// Smem: 2 logical rows (64B each) packed per 128B physical row + SW128 XOR
// => conflict-free ldmatrix. 32KB static smem.
// =====================================================================
__global__ __launch_bounds__(256) void scores_mma_kernel()
{
    __shared__ __align__(128) uint8_t smA[2][8192];
    __shared__ __align__(128) uint8_t smB[2][8192];

    const int tid = threadIdx.x;
    const int wid = tid >> 5, lid = tid & 31;
    const int b  = blockIdx.z;
    const int m0 = blockIdx.y * 128;
    const int n0 = blockIdx.x * 128;
    const int wm = wid >> 1;   // 0..3 : 32-row block
    const int wn = wid & 1;    // 0..1 : 64-col block

    const __nv_bfloat16* Ap[3] = { g_Qhi, g_Qlo, g_Qhi };
    const __nv_bfloat16* Bp[3] = { g_Khi, g_Khi, g_Klo };

    // ---- global load mapping: thread -> (row, two 16B chunks) ----
    const int grow = tid >> 1;           // 0..127
    const int gc0  = (tid & 1) * 2;      // 16B-chunk index base (0 or 2)
    const size_t aoff = (size_t)(b * S_ + m0 + grow) * KC_;
    const size_t boff = (size_t)(b * S_ + n0 + grow) * KC_;

    // smem store offsets (pair-packed + swizzle)
    const int spr = grow >> 1, sh = grow & 1;
    uint32_t st_off[2];
#pragma unroll
    for (int q = 0; q < 2; q++) {
        int pos = sh * 4 + gc0 + q;
        st_off[q] = (uint32_t)(spr * 128 + (pos ^ (spr & 7)) * 16);
    }

    // ---- ldmatrix source offsets (stage-relative) ----
    uint32_t offA[2][2];   // [mt][ks]
#pragma unroll
    for (int mt = 0; mt < 2; mt++)
#pragma unroll
        for (int ks = 0; ks < 2; ks++) {
            int r = wm * 32 + mt * 16 + (lid & 15);
            int c16 = ks * 2 + (lid >> 4);
            int pr = r >> 1, hh = r & 1;
            int pos = hh * 4 + c16;
            offA[mt][ks] = (uint32_t)(pr * 128 + (pos ^ (pr & 7)) * 16);
        }
    uint32_t offB[4][2];   // [ntp][ks]
#pragma unroll
    for (int ntp = 0; ntp < 4; ntp++)
#pragma unroll
        for (int ks = 0; ks < 2; ks++) {
            int rn = wn * 64 + ntp * 16 + (lid & 7) + ((lid >> 4) & 1) * 8;
            int c16 = ks * 2 + ((lid >> 3) & 1);
            int pr = rn >> 1, hh = rn & 1;
            int pos = hh * 4 + c16;
            offB[ntp][ks] = (uint32_t)(pr * 128 + (pos ^ (pr & 7)) * 16);
        }

    float acc[2][8][4];
#pragma unroll
    for (int mt = 0; mt < 2; mt++)
#pragma unroll
        for (int nt = 0; nt < 8; nt++)
#pragma unroll
            for (int i = 0; i < 4; i++) acc[mt][nt][i] = 0.f;

    const uint32_t aB0 = smem_u32(&smA[0][0]), aB1 = smem_u32(&smA[1][0]);
    const uint32_t bB0 = smem_u32(&smB[0][0]), bB1 = smem_u32(&smB[1][0]);

    uint4 ra[2], rb[2];
    // prefetch + store chunk 0 into stage 0
#pragma unroll
    for (int q = 0; q < 2; q++) {
        ra[q] = *(const uint4*)(Ap[0] + aoff + (gc0 + q) * 8);
        rb[q] = *(const uint4*)(Bp[0] + boff + (gc0 + q) * 8);
    }
#pragma unroll
    for (int q = 0; q < 2; q++) {
        *(uint4*)(&smA[0][0] + st_off[q]) = ra[q];
        *(uint4*)(&smB[0][0] + st_off[q]) = rb[q];
    }

    const int NIT = 96;   // 3 passes x (1024/32)
    for (int c = 0; c < NIT; c++) {
        if (c + 1 < NIT) {
            const int p  = (c + 1) >> 5;
            const int k0 = ((c + 1) & 31) * 32;
            const __nv_bfloat16* A = Ap[p];
            const __nv_bfloat16* Bq = Bp[p];
#pragma unroll
            for (int q = 0; q < 2; q++) {
                ra[q] = *(const uint4*)(A  + aoff + k0 + (gc0 + q) * 8);
                rb[q] = *(const uint4*)(Bq + boff + k0 + (gc0 + q) * 8);
            }
        }
        __syncthreads();   // stage (c&1) fully populated

        const uint32_t aBase = (c & 1) ? aB1 : aB0;
        const uint32_t bBase = (c & 1) ? bB1 : bB0;
#pragma unroll
        for (int ks = 0; ks < 2; ks++) {
            uint32_t af[2][4];
            ldsm_x4(aBase + offA[0][ks], af[0][0], af[0][1], af[0][2], af[0][3]);
            ldsm_x4(aBase + offA[1][ks], af[1][0], af[1][1], af[1][2], af[1][3]);
            uint32_t bf[8][2];
#pragma unroll
            for (int ntp = 0; ntp < 4; ntp++)
                ldsm_x4(bBase + offB[ntp][ks],
                        bf[2*ntp][0], bf[2*ntp][1], bf[2*ntp+1][0], bf[2*ntp+1][1]);
#pragma unroll
            for (int mt = 0; mt < 2; mt++)
#pragma unroll
                for (int nt = 0; nt < 8; nt++)
                    mma_bf16(acc[mt][nt], af[mt], bf[nt]);
        }

        if (c + 1 < NIT) {
            uint8_t* sa = ((c + 1) & 1) ? &smA[1][0] : &smA[0][0];
            uint8_t* sb = ((c + 1) & 1) ? &smB[1][0] : &smB[0][0];
#pragma unroll
            for (int q = 0; q < 2; q++) {
                *(uint4*)(sa + st_off[q]) = ra[q];
                *(uint4*)(sb + st_off[q]) = rb[q];
            }
        }
    }

    // ---- epilogue: lane l holds rows (l>>2, l>>2+8), cols (l&3)*2 per frag
#pragma unroll
    for (int mt = 0; mt < 2; mt++) {
        const int row = m0 + wm * 32 + mt * 16 + (lid >> 2);
        float* Sr = g_S + ((size_t)b * S_ + row) * S_;
#pragma unroll
        for (int nt = 0; nt < 8; nt++) {
            const int col = n0 + wn * 64 + nt * 8 + (lid & 3) * 2;
            *(float2*)(Sr + col)            = make_float2(acc[mt][nt][0], acc[mt][nt][1]);
            *(float2*)(Sr + 8 * S_ + col)   = make_float2(acc[mt][nt][2], acc[mt][nt][3]);
        }
    }
}

// =====================================================================
// Row softmax over 2048 cols, in place.
// =====================================================================
__global__ __launch_bounds__(256) void softmax_kernel()
{
    __shared__ float sh[8];
    float* p = g_S + (size_t)blockIdx.x * S_;
    const int t = threadIdx.x;

    float4 v0 = *(float4*)(p + t*4);
    float4 v1 = *(float4*)(p + 1024 + t*4);

    float m = fmaxf(fmaxf(fmaxf(v0.x, v0.y), fmaxf(v0.z, v0.w)),
                    fmaxf(fmaxf(v1.x, v1.y), fmaxf(v1.z, v1.w)));
#pragma unroll
    for (int o = 16; o; o >>= 1) m = fmaxf(m, __shfl_xor_sync(0xffffffffu, m, o));
    if ((t & 31) == 0) sh[t >> 5] = m;
    __syncthreads();
    m = sh[0];
#pragma unroll
    for (int i = 1; i < 8; i++) m = fmaxf(m, sh[i]);
    __syncthreads();

    v0.x = __expf(v0.x - m); v0.y = __expf(v0.y - m);
    v0.z = __expf(v0.z - m); v0.w = __expf(v0.w - m);
    v1.x = __expf(v1.x - m); v1.y = __expf(v1.y - m);
    v1.z = __expf(v1.z - m); v1.w = __expf(v1.w - m);

    float s = (v0.x + v0.y) + (v0.z + v0.w) + (v1.x + v1.y) + (v1.z + v1.w);
#pragma unroll
    for (int o = 16; o; o >>= 1) s += __shfl_xor_sync(0xffffffffu, s, o);
    if ((t & 31) == 0) sh[t >> 5] = s;
    __syncthreads();
    s = (sh[0] + sh[1]) + (sh[2] + sh[3]) + (sh[4] + sh[5]) + (sh[6] + sh[7]);
    const float inv = 1.0f / s;

    v0.x *= inv; v0.y *= inv; v0.z *= inv; v0.w *= inv;
    v1.x *= inv; v1.y *= inv; v1.z *= inv; v1.w *= inv;
    *(float4*)(p + t*4) = v0;
    *(float4*)(p + 1024 + t*4) = v1;
}

// =====================================================================
// AV (REAL PART ONLY): out = attn @ Vre  (fp32 FFMA)
// =====================================================================
__global__ __launch_bounds__(256) void av_kernel(float* __restrict__ out)
{
    __shared__ __align__(16) float As[BK*LDS_PAD];
    __shared__ __align__(16) float Bsr[BK*LDS_PAD];

    const int b = blockIdx.z;
    const float* attn = g_S + (size_t)b * S_ * S_;
    const float* vre = g_Vre + (size_t)b * S_ * D_;

    const int tid = threadIdx.x;
    const int m0 = blockIdx.y * BM;
    const int n0 = blockIdx.x * BN;
    const int ty = tid >> 4, tx = tid & 15;
    const int lrow = tid >> 2;
    const int lcol = (tid & 3) * 4;
    const int brow = tid >> 4;
    const int bcol = (tid & 15) * 4;

    float4 accre[4];
#pragma unroll
    for (int i = 0; i < 4; i++) accre[i] = make_float4(0.f, 0.f, 0.f, 0.f);

    for (int k0 = 0; k0 < S_; k0 += BK) {
        float4 a   = *(const float4*)(attn + (size_t)(m0 + lrow) * S_ + k0 + lcol);
        float4 b_r = *(const float4*)(vre + (size_t)(k0 + brow) * D_ + n0 + bcol);
        __syncthreads();
        As[(lcol+0)*LDS_PAD + lrow] = a.x; As[(lcol+1)*LDS_PAD + lrow] = a.y;
        As[(lcol+2)*LDS_PAD + lrow] = a.z; As[(lcol+3)*LDS_PAD + lrow] = a.w;
        *(float4*)&Bsr[brow*LDS_PAD + bcol] = b_r;
        __syncthreads();
#pragma unroll
        for (int k = 0; k < BK; k++) {
            float4 av = *(const float4*)&As[k*LDS_PAD + ty*4];
            float4 vr = *(const float4*)&Bsr[k*LDS_PAD + tx*4];
            sfma4(accre[0], av.x, vr);
            sfma4(accre[1], av.y, vr);
            sfma4(accre[2], av.z, vr);
            sfma4(accre[3], av.w, vr);
        }
    }

#pragma unroll
    for (int i = 0; i < 4; i++) {
        const int m = m0 + ty*4 + i;
        *(float4*)(out + ((size_t)b * S_ + m) * D_ + n0 + tx*4) = accre[i];
    }
}

// =====================================================================
extern "C" void kernel_launch(void* const* d_in, const int* in_sizes, int n_in,
                              void* d_out, int out_size)
{
    (void)in_sizes; (void)n_in; (void)out_size;

    const float* xre   = (const float*)d_in[0];
    const float* xim   = (const float*)d_in[1];
    const float* Wq_re = (const float*)d_in[2];
    const float* Wq_im = (const float*)d_in[3];
    const float* bq_re = (const float*)d_in[4];
    const float* bq_im = (const float*)d_in[5];
    const float* Wk_re = (const float*)d_in[6];
    const float* Wk_im = (const float*)d_in[7];
    const float* bk_re = (const float*)d_in[8];
    const float* bk_im = (const float*)d_in[9];
    const float* Wv_re = (const float*)d_in[10];
    const float* Wv_im = (const float*)d_in[11];
    const float* bv_re = (const float*)d_in[12];
    const float* bv_im = (const float*)d_in[13];

    dim3 projGrid(D_/BN, M_/BM);
    proj_kernel<<<projGrid, 256>>>(xre, xim, Wq_re, Wq_im, bq_re, bq_im, 0);
    proj_kernel<<<projGrid, 256>>>(xre, xim, Wk_re, Wk_im, bk_re, bk_im, 1);
    proj_kernel<<<projGrid, 256>>>(xre, xim, Wv_re, Wv_im, bv_re, bv_im, 2);

    split_convert_kernel<<<(M_ * (KC_/4)) / 256, 256>>>();

    dim3 scGrid(S_/128, S_/128, B_);     // (16, 16, 4)
    scores_mma_kernel<<<scGrid, 256>>>();

    softmax_kernel<<<B_*S_, 256>>>();

    dim3 avGrid(D_/BN, S_/BM, B_);
    av_kernel<<<avGrid, 256>>>((float*)d_out);
}

// round 12
// speedup vs baseline: 1.5668x; 1.2432x over previous
#include <cuda_runtime.h>
#include <cuda_bf16.h>
#include <cstdint>

#define D_ 512
#define S_ 2048
#define B_ 4
#define M_ (B_*S_)
#define KC_ 1024   // concat(re,im) contraction length

// ---- scratch (device globals; no allocation allowed) ----
__device__ __align__(16) float g_Qre[M_*D_], g_Qim[M_*D_];
__device__ __align__(16) float g_Kre[M_*D_], g_Kim[M_*D_];
__device__ __align__(16) float g_Vre[M_*D_], g_Vim[M_*D_];
__device__ __align__(16) float g_S[(size_t)B_*S_*S_];
__device__ __align__(16) __nv_bfloat16 g_Qhi[(size_t)M_*KC_], g_Qlo[(size_t)M_*KC_];
__device__ __align__(16) __nv_bfloat16 g_Khi[(size_t)M_*KC_], g_Klo[(size_t)M_*KC_];
// new scratch for tensorized proj / AV
__device__ __align__(16) __nv_bfloat16 g_Xhi[(size_t)M_*KC_], g_Xlo[(size_t)M_*KC_];
__device__ __align__(16) __nv_bfloat16 g_WBhi[3][(size_t)KC_*KC_], g_WBlo[3][(size_t)KC_*KC_];
__device__ __align__(16) __nv_bfloat16 g_Phi[(size_t)B_*S_*S_], g_Plo[(size_t)B_*S_*S_];
__device__ __align__(16) __nv_bfloat16 g_Vthi[(size_t)B_*D_*S_], g_Vtlo[(size_t)B_*D_*S_];

// =====================================================================
// mma.sync helpers (baseline PTX, sm_80+; compiles for compute_103)
// =====================================================================
static __device__ __forceinline__ uint32_t smem_u32(const void* p) {
    uint32_t a;
    asm("{ .reg .u64 t; cvta.to.shared.u64 t, %1; cvt.u32.u64 %0, t; }"
        : "=r"(a) : "l"(p));
    return a;
}
static __device__ __forceinline__ void ldsm_x4(uint32_t addr, uint32_t& r0,
                                               uint32_t& r1, uint32_t& r2, uint32_t& r3) {
    asm volatile("ldmatrix.sync.aligned.m8n8.x4.shared.b16 {%0,%1,%2,%3}, [%4];"
                 : "=r"(r0), "=r"(r1), "=r"(r2), "=r"(r3) : "r"(addr));
}
static __device__ __forceinline__ void mma_bf16(float* d, const uint32_t* a,
                                                const uint32_t* b) {
    asm volatile("mma.sync.aligned.m16n8k16.row.col.f32.bf16.bf16.f32 "
                 "{%0,%1,%2,%3}, {%4,%5,%6,%7}, {%8,%9}, {%0,%1,%2,%3};"
                 : "+f"(d[0]), "+f"(d[1]), "+f"(d[2]), "+f"(d[3])
                 : "r"(a[0]), "r"(a[1]), "r"(a[2]), "r"(a[3]),
                   "r"(b[0]), "r"(b[1]));
}
static __device__ __forceinline__ void split_store4(
    __nv_bfloat16* hi, __nv_bfloat16* lo, size_t off, float4 v) {
    __nv_bfloat16 h0 = __float2bfloat16_rn(v.x), h1 = __float2bfloat16_rn(v.y);
    __nv_bfloat16 h2 = __float2bfloat16_rn(v.z), h3 = __float2bfloat16_rn(v.w);
    *(__nv_bfloat162*)(hi + off)     = __nv_bfloat162(h0, h1);
    *(__nv_bfloat162*)(hi + off + 2) = __nv_bfloat162(h2, h3);
    *(__nv_bfloat162*)(lo + off)     = __nv_bfloat162(
        __float2bfloat16_rn(v.x - __bfloat162float(h0)),
        __float2bfloat16_rn(v.y - __bfloat162float(h1)));
    *(__nv_bfloat162*)(lo + off + 2) = __nv_bfloat162(
        __float2bfloat16_rn(v.z - __bfloat162float(h2)),
        __float2bfloat16_rn(v.w - __bfloat162float(h3)));
}

// =====================================================================
// Converts
// =====================================================================
// xcat = [x_re || x_im] -> g_Xhi/g_Xlo  [M_][1024]
__global__ __launch_bounds__(256) void xsplit_kernel(
    const float* __restrict__ xre, const float* __restrict__ xim)
{
    const size_t idx = (size_t)blockIdx.x * 256 + threadIdx.x;
    const size_t row = idx >> 8;
    const int c4 = (int)(idx & 255) * 4;
    const size_t soff = row * D_ + ((c4 < D_) ? c4 : c4 - D_);
    const float4 v = (c4 < D_) ? *(const float4*)(xre + soff)
                               : *(const float4*)(xim + soff);
    split_store4(g_Xhi, g_Xlo, row * KC_ + c4, v);
}

// Bcat[n][k]: n<512: [W_re | -W_im]; n>=512: [W_im | W_re]  -> g_WBhi/lo[w]
__global__ __launch_bounds__(256) void wsplit_kernel(
    const float* __restrict__ Wre, const float* __restrict__ Wim, int w)
{
    const size_t idx = (size_t)blockIdx.x * 256 + threadIdx.x;
    const int n = (int)(idx >> 8);
    const int c4 = (int)(idx & 255) * 4;
    float4 v;
    if (n < D_) {
        if (c4 < D_) v = *(const float4*)(Wre + (size_t)n * D_ + c4);
        else {
            v = *(const float4*)(Wim + (size_t)n * D_ + c4 - D_);
            v.x = -v.x; v.y = -v.y; v.z = -v.z; v.w = -v.w;
        }
    } else {
        if (c4 < D_) v = *(const float4*)(Wim + (size_t)(n - D_) * D_ + c4);
        else         v = *(const float4*)(Wre + (size_t)(n - D_) * D_ + c4 - D_);
    }
    split_store4(g_WBhi[w], g_WBlo[w], (size_t)n * KC_ + c4, v);
}

// Q/K fp32 -> bf16 hi/lo, cols = re||im (for scores)
__global__ __launch_bounds__(256) void split_convert_kernel()
{
    const size_t idx = (size_t)blockIdx.x * blockDim.x + threadIdx.x;
    const size_t row = idx >> 8;
    const int c4 = (int)(idx & 255) * 4;
    const size_t soff = (c4 < D_) ? (row * D_ + c4) : (row * D_ + (c4 - D_));
    const float4 q = (c4 < D_) ? *(const float4*)(g_Qre + soff)
                               : *(const float4*)(g_Qim + soff);
    const float4 k = (c4 < D_) ? *(const float4*)(g_Kre + soff)
                               : *(const float4*)(g_Kim + soff);
    split_store4(g_Qhi, g_Qlo, row * KC_ + c4, q);
    split_store4(g_Khi, g_Klo, row * KC_ + c4, k);
}

// attn fp32 -> hi/lo bf16 (after softmax)
__global__ __launch_bounds__(256) void psplit_kernel()
{
    const size_t idx = (size_t)blockIdx.x * 256 + threadIdx.x;
    const size_t row = idx >> 9;
    const int c4 = (int)(idx & 511) * 4;
    const float4 v = *(const float4*)(g_S + row * S_ + c4);
    split_store4(g_Phi, g_Plo, row * S_ + c4, v);
}

// V_re fp32 [b][t][e] -> Vt hi/lo bf16 [b][e][t]
__global__ void vtrans_kernel()
{
    __shared__ float sm[32][33];
    const int b = blockIdx.z;
    const int e0 = blockIdx.x * 32, t0 = blockIdx.y * 32;
    const int tx = threadIdx.x, ty = threadIdx.y;  // 32 x 8
    const float* src = g_Vre + (size_t)b * S_ * D_;
#pragma unroll
    for (int i = 0; i < 4; i++)
        sm[ty + i*8][tx] = src[(size_t)(t0 + ty + i*8) * D_ + e0 + tx];
    __syncthreads();
    const size_t dbase = (size_t)b * D_ * S_;
#pragma unroll
    for (int i = 0; i < 4; i++) {
        const int e = e0 + ty + i*8, t = t0 + tx;
        const float v = sm[tx][ty + i*8];
        const __nv_bfloat16 h = __float2bfloat16_rn(v);
        g_Vthi[dbase + (size_t)e * S_ + t] = h;
        g_Vtlo[dbase + (size_t)e * S_ + t] =
            __float2bfloat16_rn(v - __bfloat162float(h));
    }
}

// =====================================================================
// Parametric mma GEMM: modes 0/1/2 = proj Q/K/V (M=8192,N=1024,K=1024),
// mode 3 = AV (per-batch M=2048,N=512,K=2048). 3-pass split-2, CTA 128x128.
// =====================================================================
__global__ __launch_bounds__(256) void gemm_mma_kernel(
    int mode, const float* __restrict__ bre, const float* __restrict__ bim,
    float* __restrict__ outp)
{
    __shared__ __align__(128) uint8_t smA[2][8192];
    __shared__ __align__(128) uint8_t smB[2][8192];

    const int tid = threadIdx.x;
    const int wid = tid >> 5, lid = tid & 31;
    const int z  = blockIdx.z;
    const int m0 = blockIdx.y * 128;
    const int n0 = blockIdx.x * 128;
    const int wm = wid >> 1, wn = wid & 1;

    const __nv_bfloat16 *A0, *A1, *A2, *B0, *B1, *B2;
    int lda, Kpass;
    size_t abase, bbase;
    if (mode < 3) {
        A0 = g_Xhi; A1 = g_Xlo; A2 = g_Xhi;
        B0 = g_WBhi[mode]; B1 = g_WBhi[mode]; B2 = g_WBlo[mode];
        lda = KC_; Kpass = KC_;
        abase = 0; bbase = 0;
    } else {
        A0 = g_Phi; A1 = g_Plo; A2 = g_Phi;
        B0 = g_Vthi; B1 = g_Vthi; B2 = g_Vtlo;
        lda = S_; Kpass = S_;
        abase = (size_t)z * S_ * S_;
        bbase = (size_t)z * D_ * S_;
    }
    const int NIT = 3 * (Kpass / 32);

    const int grow = tid >> 1;
    const int gc0  = (tid & 1) * 2;
    const size_t aoff = abase + (size_t)(m0 + grow) * lda;
    const size_t boff = bbase + (size_t)(n0 + grow) * lda;

    const int spr = grow >> 1, sh = grow & 1;
    uint32_t st_off[2];
#pragma unroll
    for (int q = 0; q < 2; q++) {
        int pos = sh * 4 + gc0 + q;
        st_off[q] = (uint32_t)(spr * 128 + (pos ^ (spr & 7)) * 16);
    }

    uint32_t offA[2][2];
#pragma unroll
    for (int mt = 0; mt < 2; mt++)
#pragma unroll
        for (int ks = 0; ks < 2; ks++) {
            int r = wm * 32 + mt * 16 + (lid & 15);
            int c16 = ks * 2 + (lid >> 4);
            int pr = r >> 1, hh = r & 1;
            int pos = hh * 4 + c16;
            offA[mt][ks] = (uint32_t)(pr * 128 + (pos ^ (pr & 7)) * 16);
        }
    uint32_t offB[4][2];
#pragma unroll
    for (int ntp = 0; ntp < 4; ntp++)
#pragma unroll
        for (int ks = 0; ks < 2; ks++) {
            int rn = wn * 64 + ntp * 16 + (lid & 7) + ((lid >> 4) & 1) * 8;
            int c16 = ks * 2 + ((lid >> 3) & 1);
            int pr = rn >> 1, hh = rn & 1;
            int pos = hh * 4 + c16;
            offB[ntp][ks] = (uint32_t)(pr * 128 + (pos ^ (pr & 7)) * 16);
        }

    float acc[2][8][4];
#pragma unroll
    for (int mt = 0; mt < 2; mt++)
#pragma unroll
        for (int nt = 0; nt < 8; nt++)
#pragma unroll
            for (int i = 0; i < 4; i++) acc[mt][nt][i] = 0.f;

    const uint32_t aB0 = smem_u32(&smA[0][0]), aB1 = smem_u32(&smA[1][0]);
    const uint32_t bB0 = smem_u32(&smB[0][0]), bB1 = smem_u32(&smB[1][0]);

    uint4 ra[2], rb[2];
#pragma unroll
    for (int q = 0; q < 2; q++) {
        ra[q] = *(const uint4*)(A0 + aoff + (gc0 + q) * 8);
        rb[q] = *(const uint4*)(B0 + boff + (gc0 + q) * 8);
    }
#pragma unroll
    for (int q = 0; q < 2; q++) {
        *(uint4*)(&smA[0][0] + st_off[q]) = ra[q];
        *(uint4*)(&smB[0][0] + st_off[q]) = rb[q];
    }

    int pp = 0, kk = 0;   // coords of next chunk to load
    for (int c = 0; c < NIT; c++) {
        const bool have_next = (c + 1 < NIT);
        if (have_next) {
            kk += 32;
            if (kk == Kpass) { kk = 0; pp++; }
            const __nv_bfloat16* A  = (pp == 0) ? A0 : (pp == 1) ? A1 : A2;
            const __nv_bfloat16* Bq = (pp == 0) ? B0 : (pp == 1) ? B1 : B2;
#pragma unroll
            for (int q = 0; q < 2; q++) {
                ra[q] = *(const uint4*)(A  + aoff + kk + (gc0 + q) * 8);
                rb[q] = *(const uint4*)(Bq + boff + kk + (gc0 + q) * 8);
            }
        }
        __syncthreads();

        const uint32_t aBase = (c & 1) ? aB1 : aB0;
        const uint32_t bBase = (c & 1) ? bB1 : bB0;
#pragma unroll
        for (int ks = 0; ks < 2; ks++) {
            uint32_t af[2][4];
            ldsm_x4(aBase + offA[0][ks], af[0][0], af[0][1], af[0][2], af[0][3]);
            ldsm_x4(aBase + offA[1][ks], af[1][0], af[1][1], af[1][2], af[1][3]);
            uint32_t bf[8][2];
#pragma unroll
            for (int ntp = 0; ntp < 4; ntp++)
                ldsm_x4(bBase + offB[ntp][ks],
                        bf[2*ntp][0], bf[2*ntp][1], bf[2*ntp+1][0], bf[2*ntp+1][1]);
#pragma unroll
            for (int mt = 0; mt < 2; mt++)
#pragma unroll
                for (int nt = 0; nt < 8; nt++)
                    mma_bf16(acc[mt][nt], af[mt], bf[nt]);
        }

        if (have_next) {
            uint8_t* sa = ((c + 1) & 1) ? &smA[1][0] : &smA[0][0];
            uint8_t* sb = ((c + 1) & 1) ? &smB[1][0] : &smB[0][0];
#pragma unroll
            for (int q = 0; q < 2; q++) {
                *(uint4*)(sa + st_off[q]) = ra[q];
                *(uint4*)(sb + st_off[q]) = rb[q];
            }
        }
    }

    // ---- epilogue ----
    if (mode < 3) {
        float* yre = (mode == 0) ? g_Qre : (mode == 1) ? g_Kre : g_Vre;
        float* yim = (mode == 0) ? g_Qim : (mode == 1) ? g_Kim : g_Vim;
#pragma unroll
        for (int mt = 0; mt < 2; mt++) {
            const int row = m0 + wm * 32 + mt * 16 + (lid >> 2);
#pragma unroll
            for (int nt = 0; nt < 8; nt++) {
                const int col = n0 + wn * 64 + nt * 8 + (lid & 3) * 2;
                float* dst; int cc; float b0, b1;
                if (col < D_) { dst = yre; cc = col;       b0 = bre[cc]; b1 = bre[cc+1]; }
                else          { dst = yim; cc = col - D_;  b0 = bim[cc]; b1 = bim[cc+1]; }
                *(float2*)(dst + (size_t)row * D_ + cc) =
                    make_float2(acc[mt][nt][0] + b0, acc[mt][nt][1] + b1);
                *(float2*)(dst + (size_t)(row + 8) * D_ + cc) =
                    make_float2(acc[mt][nt][2] + b0, acc[mt][nt][3] + b1);
            }
        }
    } else {
#pragma unroll
        for (int mt = 0; mt < 2; mt++) {
            const int row = m0 + wm * 32 + mt * 16 + (lid >> 2);
            float* o = outp + ((size_t)z * S_ + row) * D_;
#pragma unroll
            for (int nt = 0; nt < 8; nt++) {
                const int col = n0 + wn * 64 + nt * 8 + (lid & 3) * 2;
                *(float2*)(o + col)           = make_float2(acc[mt][nt][0], acc[mt][nt][1]);
                *(float2*)(o + 8 * D_ + col)  = make_float2(acc[mt][nt][2], acc[mt][nt][3]);
            }
        }
    }
}

// =====================================================================
// Scores via mma.sync bf16 (unchanged from R11, proven)
// =====================================================================
__global__ __launch_bounds__(256) void scores_mma_kernel()
{
    __shared__ __align__(128) uint8_t smA[2][8192];
    __shared__ __align__(128) uint8_t smB[2][8192];

    const int tid = threadIdx.x;
    const int wid = tid >> 5, lid = tid & 31;
    const int b  = blockIdx.z;
    const int m0 = blockIdx.y * 128;
    const int n0 = blockIdx.x * 128;
    const int wm = wid >> 1;
    const int wn = wid & 1;

    const __nv_bfloat16* Ap[3] = { g_Qhi, g_Qlo, g_Qhi };
    const __nv_bfloat16* Bp[3] = { g_Khi, g_Khi, g_Klo };

    const int grow = tid >> 1;
    const int gc0  = (tid & 1) * 2;
    const size_t aoff = (size_t)(b * S_ + m0 + grow) * KC_;
    const size_t boff = (size_t)(b * S_ + n0 + grow) * KC_;

    const int spr = grow >> 1, sh = grow & 1;
    uint32_t st_off[2];
#pragma unroll
    for (int q = 0; q < 2; q++) {
        int pos = sh * 4 + gc0 + q;
        st_off[q] = (uint32_t)(spr * 128 + (pos ^ (spr & 7)) * 16);
    }

    uint32_t offA[2][2];
#pragma unroll
    for (int mt = 0; mt < 2; mt++)
#pragma unroll
        for (int ks = 0; ks < 2; ks++) {
            int r = wm * 32 + mt * 16 + (lid & 15);
            int c16 = ks * 2 + (lid >> 4);
            int pr = r >> 1, hh = r & 1;
            int pos = hh * 4 + c16;
            offA[mt][ks] = (uint32_t)(pr * 128 + (pos ^ (pr & 7)) * 16);
        }
    uint32_t offB[4][2];
#pragma unroll
    for (int ntp = 0; ntp < 4; ntp++)
#pragma unroll
        for (int ks = 0; ks < 2; ks++) {
            int rn = wn * 64 + ntp * 16 + (lid & 7) + ((lid >> 4) & 1) * 8;
            int c16 = ks * 2 + ((lid >> 3) & 1);
            int pr = rn >> 1, hh = rn & 1;
            int pos = hh * 4 + c16;
            offB[ntp][ks] = (uint32_t)(pr * 128 + (pos ^ (pr & 7)) * 16);
        }

    float acc[2][8][4];
#pragma unroll
    for (int mt = 0; mt < 2; mt++)
#pragma unroll
        for (int nt = 0; nt < 8; nt++)
#pragma unroll
            for (int i = 0; i < 4; i++) acc[mt][nt][i] = 0.f;

    const uint32_t aB0 = smem_u32(&smA[0][0]), aB1 = smem_u32(&smA[1][0]);
    const uint32_t bB0 = smem_u32(&smB[0][0]), bB1 = smem_u32(&smB[1][0]);

    uint4 ra[2], rb[2];
#pragma unroll
    for (int q = 0; q < 2; q++) {
        ra[q] = *(const uint4*)(Ap[0] + aoff + (gc0 + q) * 8);
        rb[q] = *(const uint4*)(Bp[0] + boff + (gc0 + q) * 8);
    }
#pragma unroll
    for (int q = 0; q < 2; q++) {
        *(uint4*)(&smA[0][0] + st_off[q]) = ra[q];
        *(uint4*)(&smB[0][0] + st_off[q]) = rb[q];
    }

    const int NIT = 96;
    for (int c = 0; c < NIT; c++) {
        if (c + 1 < NIT) {
            const int p  = (c + 1) >> 5;
            const int k0 = ((c + 1) & 31) * 32;
            const __nv_bfloat16* A = Ap[p];
            const __nv_bfloat16* Bq = Bp[p];
#pragma unroll
            for (int q = 0; q < 2; q++) {
                ra[q] = *(const uint4*)(A  + aoff + k0 + (gc0 + q) * 8);
                rb[q] = *(const uint4*)(Bq + boff + k0 + (gc0 + q) * 8);
            }
        }
        __syncthreads();

        const uint32_t aBase = (c & 1) ? aB1 : aB0;
        const uint32_t bBase = (c & 1) ? bB1 : bB0;
#pragma unroll
        for (int ks = 0; ks < 2; ks++) {
            uint32_t af[2][4];
            ldsm_x4(aBase + offA[0][ks], af[0][0], af[0][1], af[0][2], af[0][3]);
            ldsm_x4(aBase + offA[1][ks], af[1][0], af[1][1], af[1][2], af[1][3]);
            uint32_t bf[8][2];
#pragma unroll
            for (int ntp = 0; ntp < 4; ntp++)
                ldsm_x4(bBase + offB[ntp][ks],
                        bf[2*ntp][0], bf[2*ntp][1], bf[2*ntp+1][0], bf[2*ntp+1][1]);
#pragma unroll
            for (int mt = 0; mt < 2; mt++)
#pragma unroll
                for (int nt = 0; nt < 8; nt++)
                    mma_bf16(acc[mt][nt], af[mt], bf[nt]);
        }

        if (c + 1 < NIT) {
            uint8_t* sa = ((c + 1) & 1) ? &smA[1][0] : &smA[0][0];
            uint8_t* sb = ((c + 1) & 1) ? &smB[1][0] : &smB[0][0];
#pragma unroll
            for (int q = 0; q < 2; q++) {
                *(uint4*)(sa + st_off[q]) = ra[q];
                *(uint4*)(sb + st_off[q]) = rb[q];
            }
        }
    }

#pragma unroll
    for (int mt = 0; mt < 2; mt++) {
        const int row = m0 + wm * 32 + mt * 16 + (lid >> 2);
        float* Sr = g_S + ((size_t)b * S_ + row) * S_;
#pragma unroll
        for (int nt = 0; nt < 8; nt++) {
            const int col = n0 + wn * 64 + nt * 8 + (lid & 3) * 2;
            *(float2*)(Sr + col)            = make_float2(acc[mt][nt][0], acc[mt][nt][1]);
            *(float2*)(Sr + 8 * S_ + col)   = make_float2(acc[mt][nt][2], acc[mt][nt][3]);
        }
    }
}

// =====================================================================
// Row softmax over 2048 cols, in place.
// =====================================================================
__global__ __launch_bounds__(256) void softmax_kernel()
{
    __shared__ float sh[8];
    float* p = g_S + (size_t)blockIdx.x * S_;
    const int t = threadIdx.x;

    float4 v0 = *(float4*)(p + t*4);
    float4 v1 = *(float4*)(p + 1024 + t*4);

    float m = fmaxf(fmaxf(fmaxf(v0.x, v0.y), fmaxf(v0.z, v0.w)),
                    fmaxf(fmaxf(v1.x, v1.y), fmaxf(v1.z, v1.w)));
#pragma unroll
    for (int o = 16; o; o >>= 1) m = fmaxf(m, __shfl_xor_sync(0xffffffffu, m, o));
    if ((t & 31) == 0) sh[t >> 5] = m;
    __syncthreads();
    m = sh[0];
#pragma unroll
    for (int i = 1; i < 8; i++) m = fmaxf(m, sh[i]);
    __syncthreads();

    v0.x = __expf(v0.x - m); v0.y = __expf(v0.y - m);
    v0.z = __expf(v0.z - m); v0.w = __expf(v0.w - m);
    v1.x = __expf(v1.x - m); v1.y = __expf(v1.y - m);
    v1.z = __expf(v1.z - m); v1.w = __expf(v1.w - m);

    float s = (v0.x + v0.y) + (v0.z + v0.w) + (v1.x + v1.y) + (v1.z + v1.w);
#pragma unroll
    for (int o = 16; o; o >>= 1) s += __shfl_xor_sync(0xffffffffu, s, o);
    if ((t & 31) == 0) sh[t >> 5] = s;
    __syncthreads();
    s = (sh[0] + sh[1]) + (sh[2] + sh[3]) + (sh[4] + sh[5]) + (sh[6] + sh[7]);
    const float inv = 1.0f / s;

    v0.x *= inv; v0.y *= inv; v0.z *= inv; v0.w *= inv;
    v1.x *= inv; v1.y *= inv; v1.z *= inv; v1.w *= inv;
    *(float4*)(p + t*4) = v0;
    *(float4*)(p + 1024 + t*4) = v1;
}

// =====================================================================
extern "C" void kernel_launch(void* const* d_in, const int* in_sizes, int n_in,
                              void* d_out, int out_size)
{
    (void)in_sizes; (void)n_in; (void)out_size;

    const float* xre   = (const float*)d_in[0];
    const float* xim   = (const float*)d_in[1];
    const float* Wq_re = (const float*)d_in[2];
    const float* Wq_im = (const float*)d_in[3];
    const float* bq_re = (const float*)d_in[4];
    const float* bq_im = (const float*)d_in[5];
    const float* Wk_re = (const float*)d_in[6];
    const float* Wk_im = (const float*)d_in[7];
    const float* bk_re = (const float*)d_in[8];
    const float* bk_im = (const float*)d_in[9];
    const float* Wv_re = (const float*)d_in[10];
    const float* Wv_im = (const float*)d_in[11];
    const float* bv_re = (const float*)d_in[12];
    const float* bv_im = (const float*)d_in[13];

    // converts for proj
    xsplit_kernel<<<(M_ * (KC_/4)) / 256, 256>>>(xre, xim);
    wsplit_kernel<<<(KC_ * (KC_/4)) / 256, 256>>>(Wq_re, Wq_im, 0);
    wsplit_kernel<<<(KC_ * (KC_/4)) / 256, 256>>>(Wk_re, Wk_im, 1);
    wsplit_kernel<<<(KC_ * (KC_/4)) / 256, 256>>>(Wv_re, Wv_im, 2);

    // projections on tensor cores
    dim3 pj(KC_/128, M_/128, 1);              // (8, 64, 1)
    gemm_mma_kernel<<<pj, 256>>>(0, bq_re, bq_im, nullptr);
    gemm_mma_kernel<<<pj, 256>>>(1, bk_re, bk_im, nullptr);
    gemm_mma_kernel<<<pj, 256>>>(2, bv_re, bv_im, nullptr);

    // V transpose+split can start as soon as V is ready
    vtrans_kernel<<<dim3(D_/32, S_/32, B_), dim3(32, 8)>>>();

    split_convert_kernel<<<(M_ * (KC_/4)) / 256, 256>>>();

    dim3 sc(S_/128, S_/128, B_);              // (16, 16, 4)
    scores_mma_kernel<<<sc, 256>>>();

    softmax_kernel<<<B_*S_, 256>>>();

    psplit_kernel<<<((size_t)B_*S_*(S_/4)) / 256, 256>>>();

    dim3 av(D_/128, S_/128, B_);              // (4, 16, 4)
    gemm_mma_kernel<<<av, 256>>>(3, nullptr, nullptr, (float*)d_out);
}

// round 13
// speedup vs baseline: 1.9144x; 1.2219x over previous
#include <cuda_runtime.h>
#include <cuda_bf16.h>
#include <cstdint>

#define D_ 512
#define S_ 2048
#define B_ 4
#define M_ (B_*S_)
#define KC_ 1024   // concat(re,im) contraction length

// ---- scratch (device globals; no allocation allowed) ----
__device__ __align__(16) float g_Vre[M_*D_];
__device__ __align__(16) float g_S[(size_t)B_*S_*S_];
__device__ __align__(16) __nv_bfloat16 g_Qhi[(size_t)M_*KC_], g_Qlo[(size_t)M_*KC_];
__device__ __align__(16) __nv_bfloat16 g_Khi[(size_t)M_*KC_], g_Klo[(size_t)M_*KC_];
__device__ __align__(16) __nv_bfloat16 g_Xhi[(size_t)M_*KC_], g_Xlo[(size_t)M_*KC_];
__device__ __align__(16) __nv_bfloat16 g_WBhi[3][(size_t)KC_*KC_], g_WBlo[3][(size_t)KC_*KC_];
__device__ __align__(16) __nv_bfloat16 g_Phi[(size_t)B_*S_*S_], g_Plo[(size_t)B_*S_*S_];
__device__ __align__(16) __nv_bfloat16 g_Vthi[(size_t)B_*D_*S_], g_Vtlo[(size_t)B_*D_*S_];

// =====================================================================
// mma.sync helpers (baseline PTX, sm_80+; compiles for compute_103)
// =====================================================================
static __device__ __forceinline__ uint32_t smem_u32(const void* p) {
    uint32_t a;
    asm("{ .reg .u64 t; cvta.to.shared.u64 t, %1; cvt.u32.u64 %0, t; }"
        : "=r"(a) : "l"(p));
    return a;
}
static __device__ __forceinline__ void ldsm_x4(uint32_t addr, uint32_t& r0,
                                               uint32_t& r1, uint32_t& r2, uint32_t& r3) {
    asm volatile("ldmatrix.sync.aligned.m8n8.x4.shared.b16 {%0,%1,%2,%3}, [%4];"
                 : "=r"(r0), "=r"(r1), "=r"(r2), "=r"(r3) : "r"(addr));
}
static __device__ __forceinline__ void mma_bf16(float* d, const uint32_t* a,
                                                const uint32_t* b) {
    asm volatile("mma.sync.aligned.m16n8k16.row.col.f32.bf16.bf16.f32 "
                 "{%0,%1,%2,%3}, {%4,%5,%6,%7}, {%8,%9}, {%0,%1,%2,%3};"
                 : "+f"(d[0]), "+f"(d[1]), "+f"(d[2]), "+f"(d[3])
                 : "r"(a[0]), "r"(a[1]), "r"(a[2]), "r"(a[3]),
                   "r"(b[0]), "r"(b[1]));
}
static __device__ __forceinline__ void split_store4(
    __nv_bfloat16* hi, __nv_bfloat16* lo, size_t off, float4 v) {
    __nv_bfloat16 h0 = __float2bfloat16_rn(v.x), h1 = __float2bfloat16_rn(v.y);
    __nv_bfloat16 h2 = __float2bfloat16_rn(v.z), h3 = __float2bfloat16_rn(v.w);
    *(__nv_bfloat162*)(hi + off)     = __nv_bfloat162(h0, h1);
    *(__nv_bfloat162*)(hi + off + 2) = __nv_bfloat162(h2, h3);
    *(__nv_bfloat162*)(lo + off)     = __nv_bfloat162(
        __float2bfloat16_rn(v.x - __bfloat162float(h0)),
        __float2bfloat16_rn(v.y - __bfloat162float(h1)));
    *(__nv_bfloat162*)(lo + off + 2) = __nv_bfloat162(
        __float2bfloat16_rn(v.z - __bfloat162float(h2)),
        __float2bfloat16_rn(v.w - __bfloat162float(h3)));
}
static __device__ __forceinline__ void split_store2(
    __nv_bfloat16* hi, __nv_bfloat16* lo, size_t off, float v0, float v1) {
    __nv_bfloat16 h0 = __float2bfloat16_rn(v0), h1 = __float2bfloat16_rn(v1);
    *(__nv_bfloat162*)(hi + off) = __nv_bfloat162(h0, h1);
    *(__nv_bfloat162*)(lo + off) = __nv_bfloat162(
        __float2bfloat16_rn(v0 - __bfloat162float(h0)),
        __float2bfloat16_rn(v1 - __bfloat162float(h1)));
}

// =====================================================================
// Converts
// =====================================================================
__global__ __launch_bounds__(256) void xsplit_kernel(
    const float* __restrict__ xre, const float* __restrict__ xim)
{
    const size_t idx = (size_t)blockIdx.x * 256 + threadIdx.x;
    const size_t row = idx >> 8;
    const int c4 = (int)(idx & 255) * 4;
    const size_t soff = row * D_ + ((c4 < D_) ? c4 : c4 - D_);
    const float4 v = (c4 < D_) ? *(const float4*)(xre + soff)
                               : *(const float4*)(xim + soff);
    split_store4(g_Xhi, g_Xlo, row * KC_ + c4, v);
}

// Bcat[n][k]: n<512: [W_re | -W_im]; n>=512: [W_im | W_re]
// (for V only rows 0..511 are generated / used)
__global__ __launch_bounds__(256) void wsplit_kernel(
    const float* __restrict__ Wre, const float* __restrict__ Wim, int w)
{
    const size_t idx = (size_t)blockIdx.x * 256 + threadIdx.x;
    const int n = (int)(idx >> 8);
    const int c4 = (int)(idx & 255) * 4;
    float4 v;
    if (n < D_) {
        if (c4 < D_) v = *(const float4*)(Wre + (size_t)n * D_ + c4);
        else {
            v = *(const float4*)(Wim + (size_t)n * D_ + c4 - D_);
            v.x = -v.x; v.y = -v.y; v.z = -v.z; v.w = -v.w;
        }
    } else {
        if (c4 < D_) v = *(const float4*)(Wim + (size_t)(n - D_) * D_ + c4);
        else         v = *(const float4*)(Wre + (size_t)(n - D_) * D_ + c4 - D_);
    }
    split_store4(g_WBhi[w], g_WBlo[w], (size_t)n * KC_ + c4, v);
}

// V_re fp32 [b][t][e] -> Vt hi/lo bf16 [b][e][t]
__global__ void vtrans_kernel()
{
    __shared__ float sm[32][33];
    const int b = blockIdx.z;
    const int e0 = blockIdx.x * 32, t0 = blockIdx.y * 32;
    const int tx = threadIdx.x, ty = threadIdx.y;  // 32 x 8
    const float* src = g_Vre + (size_t)b * S_ * D_;
#pragma unroll
    for (int i = 0; i < 4; i++)
        sm[ty + i*8][tx] = src[(size_t)(t0 + ty + i*8) * D_ + e0 + tx];
    __syncthreads();
    const size_t dbase = (size_t)b * D_ * S_;
#pragma unroll
    for (int i = 0; i < 4; i++) {
        const int e = e0 + ty + i*8, t = t0 + tx;
        const float v = sm[tx][ty + i*8];
        const __nv_bfloat16 h = __float2bfloat16_rn(v);
        g_Vthi[dbase + (size_t)e * S_ + t] = h;
        g_Vtlo[dbase + (size_t)e * S_ + t] =
            __float2bfloat16_rn(v - __bfloat162float(h));
    }
}

// =====================================================================
// Unified mma GEMM, CTA tile 256x128, 8 warps (4x2), warp tile 64x64.
// modes: 0/1 = proj Q/K (M=8192,N=1024,K=1024, epi: split-bf16 + bias)
//        2   = proj V real (M=8192,N=512,  epi: fp32 g_Vre + bias)
//        3   = AV (per-batch M=2048,N=512,K=2048, epi: fp32 d_out)
//        4   = scores (per-batch M=N=2048,K=1024, epi: fp32 g_S)
// 3-pass split-2 in all modes.
// =====================================================================
__global__ __launch_bounds__(256) void gemm_mma_kernel(
    int mode, const float* __restrict__ bre, const float* __restrict__ bim,
    float* __restrict__ outp)
{
    __shared__ __align__(128) uint8_t smA[2][16384];
    __shared__ __align__(128) uint8_t smB[2][8192];

    const int tid = threadIdx.x;
    const int wid = tid >> 5, lid = tid & 31;
    const int z  = blockIdx.z;
    const int m0 = blockIdx.y * 256;
    const int n0 = blockIdx.x * 128;
    const int wm = wid >> 1, wn = wid & 1;   // warp grid 4 x 2

    const __nv_bfloat16 *A0, *A1, *A2, *B0, *B1, *B2;
    int lda, Kpass;
    size_t abase = 0, bbase = 0;
    if (mode <= 2) {
        A0 = g_Xhi; A1 = g_Xlo; A2 = g_Xhi;
        B0 = g_WBhi[mode]; B1 = g_WBhi[mode]; B2 = g_WBlo[mode];
        lda = KC_; Kpass = KC_;
    } else if (mode == 3) {
        A0 = g_Phi; A1 = g_Plo; A2 = g_Phi;
        B0 = g_Vthi; B1 = g_Vthi; B2 = g_Vtlo;
        lda = S_; Kpass = S_;
        abase = (size_t)z * S_ * S_;
        bbase = (size_t)z * D_ * S_;
    } else {
        A0 = g_Qhi; A1 = g_Qlo; A2 = g_Qhi;
        B0 = g_Khi; B1 = g_Khi; B2 = g_Klo;
        lda = KC_; Kpass = KC_;
        abase = (size_t)z * S_ * KC_;
        bbase = (size_t)z * S_ * KC_;
    }
    const int NIT = 3 * (Kpass / 32);

    // ---- global load mapping ----
    // A: 256 rows x 64B; thread t loads row t, 4 x 16B chunks.
    const size_t aoff = abase + (size_t)(m0 + tid) * lda;
    // B: 128 rows x 64B; thread t loads row t>>1, 2 x 16B chunks.
    const int brow = tid >> 1;
    const int bc0  = (tid & 1) * 2;
    const size_t boff = bbase + (size_t)(n0 + brow) * lda;

    // smem store offsets (pair-packed rows + XOR swizzle)
    uint32_t stA[4];
    {
        const int pr = tid >> 1, h = tid & 1;
#pragma unroll
        for (int q = 0; q < 4; q++) {
            int pos = h * 4 + q;
            stA[q] = (uint32_t)(pr * 128 + (pos ^ (pr & 7)) * 16);
        }
    }
    uint32_t stB[2];
    {
        const int pr = brow >> 1, h = brow & 1;
#pragma unroll
        for (int q = 0; q < 2; q++) {
            int pos = h * 4 + bc0 + q;
            stB[q] = (uint32_t)(pr * 128 + (pos ^ (pr & 7)) * 16);
        }
    }

    // ---- ldmatrix source offsets ----
    uint32_t offA[4][2];   // [mt][ks]
#pragma unroll
    for (int mt = 0; mt < 4; mt++)
#pragma unroll
        for (int ks = 0; ks < 2; ks++) {
            int r = wm * 64 + mt * 16 + (lid & 15);
            int c16 = ks * 2 + (lid >> 4);
            int pr = r >> 1, hh = r & 1;
            int pos = hh * 4 + c16;
            offA[mt][ks] = (uint32_t)(pr * 128 + (pos ^ (pr & 7)) * 16);
        }
    uint32_t offB[4][2];   // [ntp][ks]
#pragma unroll
    for (int ntp = 0; ntp < 4; ntp++)
#pragma unroll
        for (int ks = 0; ks < 2; ks++) {
            int rn = wn * 64 + ntp * 16 + (lid & 7) + ((lid >> 4) & 1) * 8;
            int c16 = ks * 2 + ((lid >> 3) & 1);
            int pr = rn >> 1, hh = rn & 1;
            int pos = hh * 4 + c16;
            offB[ntp][ks] = (uint32_t)(pr * 128 + (pos ^ (pr & 7)) * 16);
        }

    float acc[4][8][4];
#pragma unroll
    for (int mt = 0; mt < 4; mt++)
#pragma unroll
        for (int nt = 0; nt < 8; nt++)
#pragma unroll
            for (int i = 0; i < 4; i++) acc[mt][nt][i] = 0.f;

    const uint32_t aS0 = smem_u32(&smA[0][0]), aS1 = smem_u32(&smA[1][0]);
    const uint32_t bS0 = smem_u32(&smB[0][0]), bS1 = smem_u32(&smB[1][0]);

    uint4 ra[4], rb[2];
#pragma unroll
    for (int q = 0; q < 4; q++) ra[q] = *(const uint4*)(A0 + aoff + q * 8);
#pragma unroll
    for (int q = 0; q < 2; q++) rb[q] = *(const uint4*)(B0 + boff + (bc0 + q) * 8);
#pragma unroll
    for (int q = 0; q < 4; q++) *(uint4*)(&smA[0][0] + stA[q]) = ra[q];
#pragma unroll
    for (int q = 0; q < 2; q++) *(uint4*)(&smB[0][0] + stB[q]) = rb[q];

    int pp = 0, kk = 0;
    for (int c = 0; c < NIT; c++) {
        const bool have_next = (c + 1 < NIT);
        if (have_next) {
            kk += 32;
            if (kk == Kpass) { kk = 0; pp++; }
            const __nv_bfloat16* A  = (pp == 0) ? A0 : (pp == 1) ? A1 : A2;
            const __nv_bfloat16* Bq = (pp == 0) ? B0 : (pp == 1) ? B1 : B2;
#pragma unroll
            for (int q = 0; q < 4; q++)
                ra[q] = *(const uint4*)(A + aoff + kk + q * 8);
#pragma unroll
            for (int q = 0; q < 2; q++)
                rb[q] = *(const uint4*)(Bq + boff + kk + (bc0 + q) * 8);
        }
        __syncthreads();

        const uint32_t aBase = (c & 1) ? aS1 : aS0;
        const uint32_t bBase = (c & 1) ? bS1 : bS0;
#pragma unroll
        for (int ks = 0; ks < 2; ks++) {
            uint32_t af[4][4];
#pragma unroll
            for (int mt = 0; mt < 4; mt++)
                ldsm_x4(aBase + offA[mt][ks], af[mt][0], af[mt][1], af[mt][2], af[mt][3]);
            uint32_t bf[8][2];
#pragma unroll
            for (int ntp = 0; ntp < 4; ntp++)
                ldsm_x4(bBase + offB[ntp][ks],
                        bf[2*ntp][0], bf[2*ntp][1], bf[2*ntp+1][0], bf[2*ntp+1][1]);
#pragma unroll
            for (int mt = 0; mt < 4; mt++)
#pragma unroll
                for (int nt = 0; nt < 8; nt++)
                    mma_bf16(acc[mt][nt], af[mt], bf[nt]);
        }

        if (have_next) {
            uint8_t* sa = ((c + 1) & 1) ? &smA[1][0] : &smA[0][0];
            uint8_t* sb = ((c + 1) & 1) ? &smB[1][0] : &smB[0][0];
#pragma unroll
            for (int q = 0; q < 4; q++) *(uint4*)(sa + stA[q]) = ra[q];
#pragma unroll
            for (int q = 0; q < 2; q++) *(uint4*)(sb + stB[q]) = rb[q];
        }
    }

    // ---- epilogue ----
    if (mode <= 1) {
        __nv_bfloat16* ph = (mode == 0) ? g_Qhi : g_Khi;
        __nv_bfloat16* pl = (mode == 0) ? g_Qlo : g_Klo;
#pragma unroll
        for (int mt = 0; mt < 4; mt++) {
            const int row = m0 + wm * 64 + mt * 16 + (lid >> 2);
#pragma unroll
            for (int nt = 0; nt < 8; nt++) {
                const int col = n0 + wn * 64 + nt * 8 + (lid & 3) * 2;
                const float b0 = (col < D_) ? bre[col]     : bim[col - D_];
                const float b1 = (col < D_) ? bre[col + 1] : bim[col - D_ + 1];
                split_store2(ph, pl, (size_t)row * KC_ + col,
                             acc[mt][nt][0] + b0, acc[mt][nt][1] + b1);
                split_store2(ph, pl, (size_t)(row + 8) * KC_ + col,
                             acc[mt][nt][2] + b0, acc[mt][nt][3] + b1);
            }
        }
    } else if (mode == 2) {
#pragma unroll
        for (int mt = 0; mt < 4; mt++) {
            const int row = m0 + wm * 64 + mt * 16 + (lid >> 2);
#pragma unroll
            for (int nt = 0; nt < 8; nt++) {
                const int col = n0 + wn * 64 + nt * 8 + (lid & 3) * 2;
                const float b0 = bre[col], b1 = bre[col + 1];
                *(float2*)(g_Vre + (size_t)row * D_ + col) =
                    make_float2(acc[mt][nt][0] + b0, acc[mt][nt][1] + b1);
                *(float2*)(g_Vre + (size_t)(row + 8) * D_ + col) =
                    make_float2(acc[mt][nt][2] + b0, acc[mt][nt][3] + b1);
            }
        }
    } else if (mode == 3) {
#pragma unroll
        for (int mt = 0; mt < 4; mt++) {
            const int row = m0 + wm * 64 + mt * 16 + (lid >> 2);
            float* o = outp + ((size_t)z * S_ + row) * D_;
#pragma unroll
            for (int nt = 0; nt < 8; nt++) {
                const int col = n0 + wn * 64 + nt * 8 + (lid & 3) * 2;
                *(float2*)(o + col)          = make_float2(acc[mt][nt][0], acc[mt][nt][1]);
                *(float2*)(o + 8 * D_ + col) = make_float2(acc[mt][nt][2], acc[mt][nt][3]);
            }
        }
    } else {
#pragma unroll
        for (int mt = 0; mt < 4; mt++) {
            const int row = m0 + wm * 64 + mt * 16 + (lid >> 2);
            float* Sr = g_S + ((size_t)z * S_ + row) * S_;
#pragma unroll
            for (int nt = 0; nt < 8; nt++) {
                const int col = n0 + wn * 64 + nt * 8 + (lid & 3) * 2;
                *(float2*)(Sr + col)          = make_float2(acc[mt][nt][0], acc[mt][nt][1]);
                *(float2*)(Sr + 8 * S_ + col) = make_float2(acc[mt][nt][2], acc[mt][nt][3]);
            }
        }
    }
}

// =====================================================================
// Row softmax over 2048 cols; writes split-bf16 P directly.
// =====================================================================
__global__ __launch_bounds__(256) void softmax_kernel()
{
    __shared__ float sh[8];
    const size_t row = blockIdx.x;
    const float* p = g_S + row * S_;
    const int t = threadIdx.x;

    float4 v0 = *(const float4*)(p + t*4);
    float4 v1 = *(const float4*)(p + 1024 + t*4);

    float m = fmaxf(fmaxf(fmaxf(v0.x, v0.y), fmaxf(v0.z, v0.w)),
                    fmaxf(fmaxf(v1.x, v1.y), fmaxf(v1.z, v1.w)));
#pragma unroll
    for (int o = 16; o; o >>= 1) m = fmaxf(m, __shfl_xor_sync(0xffffffffu, m, o));
    if ((t & 31) == 0) sh[t >> 5] = m;
    __syncthreads();
    m = sh[0];
#pragma unroll
    for (int i = 1; i < 8; i++) m = fmaxf(m, sh[i]);
    __syncthreads();

    v0.x = __expf(v0.x - m); v0.y = __expf(v0.y - m);
    v0.z = __expf(v0.z - m); v0.w = __expf(v0.w - m);
    v1.x = __expf(v1.x - m); v1.y = __expf(v1.y - m);
    v1.z = __expf(v1.z - m); v1.w = __expf(v1.w - m);

    float s = (v0.x + v0.y) + (v0.z + v0.w) + (v1.x + v1.y) + (v1.z + v1.w);
#pragma unroll
    for (int o = 16; o; o >>= 1) s += __shfl_xor_sync(0xffffffffu, s, o);
    if ((t & 31) == 0) sh[t >> 5] = s;
    __syncthreads();
    s = (sh[0] + sh[1]) + (sh[2] + sh[3]) + (sh[4] + sh[5]) + (sh[6] + sh[7]);
    const float inv = 1.0f / s;

    v0.x *= inv; v0.y *= inv; v0.z *= inv; v0.w *= inv;
    v1.x *= inv; v1.y *= inv; v1.z *= inv; v1.w *= inv;
    split_store4(g_Phi, g_Plo, row * S_ + t*4, v0);
    split_store4(g_Phi, g_Plo, row * S_ + 1024 + t*4, v1);
}

// =====================================================================
extern "C" void kernel_launch(void* const* d_in, const int* in_sizes, int n_in,
                              void* d_out, int out_size)
{
    (void)in_sizes; (void)n_in; (void)out_size;

    const float* xre   = (const float*)d_in[0];
    const float* xim   = (const float*)d_in[1];
    const float* Wq_re = (const float*)d_in[2];
    const float* Wq_im = (const float*)d_in[3];
    const float* bq_re = (const float*)d_in[4];
    const float* bq_im = (const float*)d_in[5];
    const float* Wk_re = (const float*)d_in[6];
    const float* Wk_im = (const float*)d_in[7];
    const float* bk_re = (const float*)d_in[8];
    const float* bk_im = (const float*)d_in[9];
    const float* Wv_re = (const float*)d_in[10];
    const float* Wv_im = (const float*)d_in[11];
    const float* bv_re = (const float*)d_in[12];
    const float* bv_im = (const float*)d_in[13];
    (void)bv_im;

    // converts
    xsplit_kernel<<<(M_ * (KC_/4)) / 256, 256>>>(xre, xim);
    wsplit_kernel<<<(KC_ * (KC_/4)) / 256, 256>>>(Wq_re, Wq_im, 0);
    wsplit_kernel<<<(KC_ * (KC_/4)) / 256, 256>>>(Wk_re, Wk_im, 1);
    wsplit_kernel<<<(D_  * (KC_/4)) / 256, 256>>>(Wv_re, Wv_im, 2);  // real rows only

    // projections (Q/K emit split-bf16 directly; V emits fp32 real part)
    dim3 pjQK(KC_/128, M_/256, 1);            // (8, 32)
    gemm_mma_kernel<<<pjQK, 256>>>(0, bq_re, bq_im, nullptr);
    gemm_mma_kernel<<<pjQK, 256>>>(1, bk_re, bk_im, nullptr);
    dim3 pjV(D_/128, M_/256, 1);              // (4, 32)
    gemm_mma_kernel<<<pjV, 256>>>(2, bv_re, nullptr, nullptr);

    vtrans_kernel<<<dim3(D_/32, S_/32, B_), dim3(32, 8)>>>();

    dim3 sc(S_/128, S_/256, B_);              // (16, 8, 4)
    gemm_mma_kernel<<<sc, 256>>>(4, nullptr, nullptr, nullptr);

    softmax_kernel<<<B_*S_, 256>>>();

    dim3 av(D_/128, S_/256, B_);              // (4, 8, 4)
    gemm_mma_kernel<<<av, 256>>>(3, nullptr, nullptr, (float*)d_out);
}

// round 14
// speedup vs baseline: 2.0203x; 1.0553x over previous
#include <cuda_runtime.h>
#include <cuda_bf16.h>
#include <cstdint>

#define D_ 512
#define S_ 2048
#define B_ 4
#define M_ (B_*S_)
#define KC_ 1024   // concat(re,im) contraction length

// ---- scratch (device globals; no allocation allowed) ----
__device__ __align__(16) float g_Vre[M_*D_];
__device__ __align__(16) float g_S[(size_t)B_*S_*S_];
__device__ __align__(16) __nv_bfloat16 g_Qhi[(size_t)M_*KC_], g_Qlo[(size_t)M_*KC_];
__device__ __align__(16) __nv_bfloat16 g_Khi[(size_t)M_*KC_], g_Klo[(size_t)M_*KC_];
__device__ __align__(16) __nv_bfloat16 g_Xhi[(size_t)M_*KC_], g_Xlo[(size_t)M_*KC_];
__device__ __align__(16) __nv_bfloat16 g_WBhi[3][(size_t)KC_*KC_], g_WBlo[3][(size_t)KC_*KC_];
__device__ __align__(16) __nv_bfloat16 g_Phi[(size_t)B_*S_*S_], g_Plo[(size_t)B_*S_*S_];
__device__ __align__(16) __nv_bfloat16 g_Vthi[(size_t)B_*D_*S_], g_Vtlo[(size_t)B_*D_*S_];

// =====================================================================
// helpers
// =====================================================================
static __device__ __forceinline__ uint32_t smem_u32(const void* p) {
    uint32_t a;
    asm("{ .reg .u64 t; cvta.to.shared.u64 t, %1; cvt.u32.u64 %0, t; }"
        : "=r"(a) : "l"(p));
    return a;
}
static __device__ __forceinline__ void ldsm_x4(uint32_t addr, uint32_t& r0,
                                               uint32_t& r1, uint32_t& r2, uint32_t& r3) {
    asm volatile("ldmatrix.sync.aligned.m8n8.x4.shared.b16 {%0,%1,%2,%3}, [%4];"
                 : "=r"(r0), "=r"(r1), "=r"(r2), "=r"(r3) : "r"(addr));
}
static __device__ __forceinline__ void mma_bf16(float* d, const uint32_t* a,
                                                const uint32_t* b) {
    asm volatile("mma.sync.aligned.m16n8k16.row.col.f32.bf16.bf16.f32 "
                 "{%0,%1,%2,%3}, {%4,%5,%6,%7}, {%8,%9}, {%0,%1,%2,%3};"
                 : "+f"(d[0]), "+f"(d[1]), "+f"(d[2]), "+f"(d[3])
                 : "r"(a[0]), "r"(a[1]), "r"(a[2]), "r"(a[3]),
                   "r"(b[0]), "r"(b[1]));
}
static __device__ __forceinline__ void split_store4(
    __nv_bfloat16* hi, __nv_bfloat16* lo, size_t off, float4 v) {
    __nv_bfloat16 h0 = __float2bfloat16_rn(v.x), h1 = __float2bfloat16_rn(v.y);
    __nv_bfloat16 h2 = __float2bfloat16_rn(v.z), h3 = __float2bfloat16_rn(v.w);
    *(__nv_bfloat162*)(hi + off)     = __nv_bfloat162(h0, h1);
    *(__nv_bfloat162*)(hi + off + 2) = __nv_bfloat162(h2, h3);
    *(__nv_bfloat162*)(lo + off)     = __nv_bfloat162(
        __float2bfloat16_rn(v.x - __bfloat162float(h0)),
        __float2bfloat16_rn(v.y - __bfloat162float(h1)));
    *(__nv_bfloat162*)(lo + off + 2) = __nv_bfloat162(
        __float2bfloat16_rn(v.z - __bfloat162float(h2)),
        __float2bfloat16_rn(v.w - __bfloat162float(h3)));
}
static __device__ __forceinline__ void split_store2(
    __nv_bfloat16* hi, __nv_bfloat16* lo, size_t off, float v0, float v1) {
    __nv_bfloat16 h0 = __float2bfloat16_rn(v0), h1 = __float2bfloat16_rn(v1);
    *(__nv_bfloat162*)(hi + off) = __nv_bfloat162(h0, h1);
    *(__nv_bfloat162*)(lo + off) = __nv_bfloat162(
        __float2bfloat16_rn(v0 - __bfloat162float(h0)),
        __float2bfloat16_rn(v1 - __bfloat162float(h1)));
}
// Fast exp on the FMA pipe (degree-5 poly, rel err ~1e-7); x <= 0 expected.
static __device__ __forceinline__ float fexp(float x) {
    x = fmaxf(x, -87.0f);
    const float n = rintf(x * 1.44269504f);
    const float r = fmaf(n, -0.693359375f, x) - n * -2.12194440e-4f;
    float p = 1.9875691500e-4f;
    p = fmaf(p, r, 1.3981999507e-3f);
    p = fmaf(p, r, 8.3334519073e-3f);
    p = fmaf(p, r, 4.1665795894e-2f);
    p = fmaf(p, r, 1.6666665459e-1f);
    p = fmaf(p, r, 5.0000001201e-1f);
    p = fmaf(p * r, r, r) + 1.0f;
    const int e = ((int)n + 127) << 23;
    return p * __int_as_float(e);
}

// =====================================================================
// Converts
// =====================================================================
__global__ __launch_bounds__(256) void xsplit_kernel(
    const float* __restrict__ xre, const float* __restrict__ xim)
{
    const size_t idx = (size_t)blockIdx.x * 256 + threadIdx.x;
    const size_t row = idx >> 8;
    const int c4 = (int)(idx & 255) * 4;
    const size_t soff = row * D_ + ((c4 < D_) ? c4 : c4 - D_);
    const float4 v = (c4 < D_) ? *(const float4*)(xre + soff)
                               : *(const float4*)(xim + soff);
    split_store4(g_Xhi, g_Xlo, row * KC_ + c4, v);
}

__global__ __launch_bounds__(256) void wsplit_kernel(
    const float* __restrict__ Wre, const float* __restrict__ Wim, int w)
{
    const size_t idx = (size_t)blockIdx.x * 256 + threadIdx.x;
    const int n = (int)(idx >> 8);
    const int c4 = (int)(idx & 255) * 4;
    float4 v;
    if (n < D_) {
        if (c4 < D_) v = *(const float4*)(Wre + (size_t)n * D_ + c4);
        else {
            v = *(const float4*)(Wim + (size_t)n * D_ + c4 - D_);
            v.x = -v.x; v.y = -v.y; v.z = -v.z; v.w = -v.w;
        }
    } else {
        if (c4 < D_) v = *(const float4*)(Wim + (size_t)(n - D_) * D_ + c4);
        else         v = *(const float4*)(Wre + (size_t)(n - D_) * D_ + c4 - D_);
    }
    split_store4(g_WBhi[w], g_WBlo[w], (size_t)n * KC_ + c4, v);
}

__global__ void vtrans_kernel()
{
    __shared__ float sm[32][33];
    const int b = blockIdx.z;
    const int e0 = blockIdx.x * 32, t0 = blockIdx.y * 32;
    const int tx = threadIdx.x, ty = threadIdx.y;  // 32 x 8
    const float* src = g_Vre + (size_t)b * S_ * D_;
#pragma unroll
    for (int i = 0; i < 4; i++)
        sm[ty + i*8][tx] = src[(size_t)(t0 + ty + i*8) * D_ + e0 + tx];
    __syncthreads();
    const size_t dbase = (size_t)b * D_ * S_;
#pragma unroll
    for (int i = 0; i < 4; i++) {
        const int e = e0 + ty + i*8, t = t0 + tx;
        const float v = sm[tx][ty + i*8];
        const __nv_bfloat16 h = __float2bfloat16_rn(v);
        g_Vthi[dbase + (size_t)e * S_ + t] = h;
        g_Vtlo[dbase + (size_t)e * S_ + t] =
            __float2bfloat16_rn(v - __bfloat162float(h));
    }
}

// =====================================================================
// Unified mma GEMM, CTA tile 128x128, 8 warps (4x2), warp tile 32x64.
// kind 0: merged proj (blockIdx.x encodes Q/K/V tile)
// kind 1: scores (per-batch, M=N=2048, K=1024)
// kind 2: AV     (per-batch, M=2048, N=512, K=2048)
// modes inside: 0/1 proj Q/K (epi split-bf16+bias), 2 proj V (fp32+bias),
//               4 scores (fp32 g_S), 3 AV (fp32 out). 3-pass split-2.
// =====================================================================
__global__ __launch_bounds__(256) void gemm_mma_kernel(
    int kind,
    const float* __restrict__ bqre, const float* __restrict__ bqim,
    const float* __restrict__ bkre, const float* __restrict__ bkim,
    const float* __restrict__ bvre,
    float* __restrict__ outp)
{
    __shared__ __align__(128) uint8_t smA[2][8192];
    __shared__ __align__(128) uint8_t smB[2][8192];

    const int tid = threadIdx.x;
    const int wid = tid >> 5, lid = tid & 31;
    const int wm = wid >> 1, wn = wid & 1;

    int mode, m0, n0, z = 0;
    if (kind == 0) {
        int t = blockIdx.x;
        if (t < 512)       { mode = 0; m0 = (t >> 3) * 128; n0 = (t & 7) * 128; }
        else if (t < 1024) { t -= 512;  mode = 1; m0 = (t >> 3) * 128; n0 = (t & 7) * 128; }
        else               { t -= 1024; mode = 2; m0 = (t >> 2) * 128; n0 = (t & 3) * 128; }
    } else if (kind == 1) {
        mode = 4; m0 = blockIdx.y * 128; n0 = blockIdx.x * 128; z = blockIdx.z;
    } else {
        mode = 3; m0 = blockIdx.y * 128; n0 = blockIdx.x * 128; z = blockIdx.z;
    }

    const __nv_bfloat16 *A0, *A1, *A2, *B0, *B1, *B2;
    int lda, Kpass;
    size_t abase = 0, bbase = 0;
    if (mode <= 2) {
        A0 = g_Xhi; A1 = g_Xlo; A2 = g_Xhi;
        B0 = g_WBhi[mode]; B1 = g_WBhi[mode]; B2 = g_WBlo[mode];
        lda = KC_; Kpass = KC_;
    } else if (mode == 3) {
        A0 = g_Phi; A1 = g_Plo; A2 = g_Phi;
        B0 = g_Vthi; B1 = g_Vthi; B2 = g_Vtlo;
        lda = S_; Kpass = S_;
        abase = (size_t)z * S_ * S_;
        bbase = (size_t)z * D_ * S_;
    } else {
        A0 = g_Qhi; A1 = g_Qlo; A2 = g_Qhi;
        B0 = g_Khi; B1 = g_Khi; B2 = g_Klo;
        lda = KC_; Kpass = KC_;
        abase = (size_t)z * S_ * KC_;
        bbase = (size_t)z * S_ * KC_;
    }
    const int NIT = 3 * (Kpass / 32);

    const int grow = tid >> 1;
    const int gc0  = (tid & 1) * 2;
    const size_t aoff = abase + (size_t)(m0 + grow) * lda;
    const size_t boff = bbase + (size_t)(n0 + grow) * lda;

    const int spr = grow >> 1, sh = grow & 1;
    uint32_t st_off[2];
#pragma unroll
    for (int q = 0; q < 2; q++) {
        int pos = sh * 4 + gc0 + q;
        st_off[q] = (uint32_t)(spr * 128 + (pos ^ (spr & 7)) * 16);
    }

    uint32_t offA[2][2];
#pragma unroll
    for (int mt = 0; mt < 2; mt++)
#pragma unroll
        for (int ks = 0; ks < 2; ks++) {
            int r = wm * 32 + mt * 16 + (lid & 15);
            int c16 = ks * 2 + (lid >> 4);
            int pr = r >> 1, hh = r & 1;
            int pos = hh * 4 + c16;
            offA[mt][ks] = (uint32_t)(pr * 128 + (pos ^ (pr & 7)) * 16);
        }
    uint32_t offB[4][2];
#pragma unroll
    for (int ntp = 0; ntp < 4; ntp++)
#pragma unroll
        for (int ks = 0; ks < 2; ks++) {
            int rn = wn * 64 + ntp * 16 + (lid & 7) + ((lid >> 4) & 1) * 8;
            int c16 = ks * 2 + ((lid >> 3) & 1);
            int pr = rn >> 1, hh = rn & 1;
            int pos = hh * 4 + c16;
            offB[ntp][ks] = (uint32_t)(pr * 128 + (pos ^ (pr & 7)) * 16);
        }

    float acc[2][8][4];
#pragma unroll
    for (int mt = 0; mt < 2; mt++)
#pragma unroll
        for (int nt = 0; nt < 8; nt++)
#pragma unroll
            for (int i = 0; i < 4; i++) acc[mt][nt][i] = 0.f;

    const uint32_t aS0 = smem_u32(&smA[0][0]), aS1 = smem_u32(&smA[1][0]);
    const uint32_t bS0 = smem_u32(&smB[0][0]), bS1 = smem_u32(&smB[1][0]);

    uint4 ra[2], rb[2];
#pragma unroll
    for (int q = 0; q < 2; q++) {
        ra[q] = *(const uint4*)(A0 + aoff + (gc0 + q) * 8);
        rb[q] = *(const uint4*)(B0 + boff + (gc0 + q) * 8);
    }
#pragma unroll
    for (int q = 0; q < 2; q++) {
        *(uint4*)(&smA[0][0] + st_off[q]) = ra[q];
        *(uint4*)(&smB[0][0] + st_off[q]) = rb[q];
    }

    int pp = 0, kk = 0;
    for (int c = 0; c < NIT; c++) {
        const bool have_next = (c + 1 < NIT);
        if (have_next) {
            kk += 32;
            if (kk == Kpass) { kk = 0; pp++; }
            const __nv_bfloat16* A  = (pp == 0) ? A0 : (pp == 1) ? A1 : A2;
            const __nv_bfloat16* Bq = (pp == 0) ? B0 : (pp == 1) ? B1 : B2;
#pragma unroll
            for (int q = 0; q < 2; q++) {
                ra[q] = *(const uint4*)(A  + aoff + kk + (gc0 + q) * 8);
                rb[q] = *(const uint4*)(Bq + boff + kk + (gc0 + q) * 8);
            }
        }
        __syncthreads();

        const uint32_t aBase = (c & 1) ? aS1 : aS0;
        const uint32_t bBase = (c & 1) ? bS1 : bS0;
#pragma unroll
        for (int ks = 0; ks < 2; ks++) {
            uint32_t af[2][4];
            ldsm_x4(aBase + offA[0][ks], af[0][0], af[0][1], af[0][2], af[0][3]);
            ldsm_x4(aBase + offA[1][ks], af[1][0], af[1][1], af[1][2], af[1][3]);
            uint32_t bf[8][2];
#pragma unroll
            for (int ntp = 0; ntp < 4; ntp++)
                ldsm_x4(bBase + offB[ntp][ks],
                        bf[2*ntp][0], bf[2*ntp][1], bf[2*ntp+1][0], bf[2*ntp+1][1]);
#pragma unroll
            for (int mt = 0; mt < 2; mt++)
#pragma unroll
                for (int nt = 0; nt < 8; nt++)
                    mma_bf16(acc[mt][nt], af[mt], bf[nt]);
        }

        if (have_next) {
            uint8_t* sa = ((c + 1) & 1) ? &smA[1][0] : &smA[0][0];
            uint8_t* sb = ((c + 1) & 1) ? &smB[1][0] : &smB[0][0];
#pragma unroll
            for (int q = 0; q < 2; q++) {
                *(uint4*)(sa + st_off[q]) = ra[q];
                *(uint4*)(sb + st_off[q]) = rb[q];
            }
        }
    }

    // ---- epilogue ----
    if (mode <= 1) {
        __nv_bfloat16* ph = (mode == 0) ? g_Qhi : g_Khi;
        __nv_bfloat16* pl = (mode == 0) ? g_Qlo : g_Klo;
        const float* bre = (mode == 0) ? bqre : bkre;
        const float* bim = (mode == 0) ? bqim : bkim;
#pragma unroll
        for (int mt = 0; mt < 2; mt++) {
            const int row = m0 + wm * 32 + mt * 16 + (lid >> 2);
#pragma unroll
            for (int nt = 0; nt < 8; nt++) {
                const int col = n0 + wn * 64 + nt * 8 + (lid & 3) * 2;
                const float b0 = (col < D_) ? bre[col]     : bim[col - D_];
                const float b1 = (col < D_) ? bre[col + 1] : bim[col - D_ + 1];
                split_store2(ph, pl, (size_t)row * KC_ + col,
                             acc[mt][nt][0] + b0, acc[mt][nt][1] + b1);
                split_store2(ph, pl, (size_t)(row + 8) * KC_ + col,
                             acc[mt][nt][2] + b0, acc[mt][nt][3] + b1);
            }
        }
    } else if (mode == 2) {
#pragma unroll
        for (int mt = 0; mt < 2; mt++) {
            const int row = m0 + wm * 32 + mt * 16 + (lid >> 2);
#pragma unroll
            for (int nt = 0; nt < 8; nt++) {
                const int col = n0 + wn * 64 + nt * 8 + (lid & 3) * 2;
                const float b0 = bvre[col], b1 = bvre[col + 1];
                *(float2*)(g_Vre + (size_t)row * D_ + col) =
                    make_float2(acc[mt][nt][0] + b0, acc[mt][nt][1] + b1);
                *(float2*)(g_Vre + (size_t)(row + 8) * D_ + col) =
                    make_float2(acc[mt][nt][2] + b0, acc[mt][nt][3] + b1);
            }
        }
    } else if (mode == 3) {
#pragma unroll
        for (int mt = 0; mt < 2; mt++) {
            const int row = m0 + wm * 32 + mt * 16 + (lid >> 2);
            float* o = outp + ((size_t)z * S_ + row) * D_;
#pragma unroll
            for (int nt = 0; nt < 8; nt++) {
                const int col = n0 + wn * 64 + nt * 8 + (lid & 3) * 2;
                *(float2*)(o + col)          = make_float2(acc[mt][nt][0], acc[mt][nt][1]);
                *(float2*)(o + 8 * D_ + col) = make_float2(acc[mt][nt][2], acc[mt][nt][3]);
            }
        }
    } else {
#pragma unroll
        for (int mt = 0; mt < 2; mt++) {
            const int row = m0 + wm * 32 + mt * 16 + (lid >> 2);
            float* Sr = g_S + ((size_t)z * S_ + row) * S_;
#pragma unroll
            for (int nt = 0; nt < 8; nt++) {
                const int col = n0 + wn * 64 + nt * 8 + (lid & 3) * 2;
                *(float2*)(Sr + col)          = make_float2(acc[mt][nt][0], acc[mt][nt][1]);
                *(float2*)(Sr + 8 * S_ + col) = make_float2(acc[mt][nt][2], acc[mt][nt][3]);
            }
        }
    }
}

// =====================================================================
// Row softmax over 2048 cols; poly exp (FMA pipe); writes split-bf16 P.
// =====================================================================
__global__ __launch_bounds__(256) void softmax_kernel()
{
    __shared__ float sh[8];
    const size_t row = blockIdx.x;
    const float* p = g_S + row * S_;
    const int t = threadIdx.x;

    float4 v0 = *(const float4*)(p + t*4);
    float4 v1 = *(const float4*)(p + 1024 + t*4);

    float m = fmaxf(fmaxf(fmaxf(v0.x, v0.y), fmaxf(v0.z, v0.w)),
                    fmaxf(fmaxf(v1.x, v1.y), fmaxf(v1.z, v1.w)));
#pragma unroll
    for (int o = 16; o; o >>= 1) m = fmaxf(m, __shfl_xor_sync(0xffffffffu, m, o));
    if ((t & 31) == 0) sh[t >> 5] = m;
    __syncthreads();
    m = sh[0];
#pragma unroll
    for (int i = 1; i < 8; i++) m = fmaxf(m, sh[i]);
    __syncthreads();

    v0.x = fexp(v0.x - m); v0.y = fexp(v0.y - m);
    v0.z = fexp(v0.z - m); v0.w = fexp(v0.w - m);
    v1.x = fexp(v1.x - m); v1.y = fexp(v1.y - m);
    v1.z = fexp(v1.z - m); v1.w = fexp(v1.w - m);

    float s = (v0.x + v0.y) + (v0.z + v0.w) + (v1.x + v1.y) + (v1.z + v1.w);
#pragma unroll
    for (int o = 16; o; o >>= 1) s += __shfl_xor_sync(0xffffffffu, s, o);
    if ((t & 31) == 0) sh[t >> 5] = s;
    __syncthreads();
    s = (sh[0] + sh[1]) + (sh[2] + sh[3]) + (sh[4] + sh[5]) + (sh[6] + sh[7]);
    const float inv = 1.0f / s;

    v0.x *= inv; v0.y *= inv; v0.z *= inv; v0.w *= inv;
    v1.x *= inv; v1.y *= inv; v1.z *= inv; v1.w *= inv;
    split_store4(g_Phi, g_Plo, row * S_ + t*4, v0);
    split_store4(g_Phi, g_Plo, row * S_ + 1024 + t*4, v1);
}

// =====================================================================
extern "C" void kernel_launch(void* const* d_in, const int* in_sizes, int n_in,
                              void* d_out, int out_size)
{
    (void)in_sizes; (void)n_in; (void)out_size;

    const float* xre   = (const float*)d_in[0];
    const float* xim   = (const float*)d_in[1];
    const float* Wq_re = (const float*)d_in[2];
    const float* Wq_im = (const float*)d_in[3];
    const float* bq_re = (const float*)d_in[4];
    const float* bq_im = (const float*)d_in[5];
    const float* Wk_re = (const float*)d_in[6];
    const float* Wk_im = (const float*)d_in[7];
    const float* bk_re = (const float*)d_in[8];
    const float* bk_im = (const float*)d_in[9];
    const float* Wv_re = (const float*)d_in[10];
    const float* Wv_im = (const float*)d_in[11];
    const float* bv_re = (const float*)d_in[12];

    // converts
    xsplit_kernel<<<(M_ * (KC_/4)) / 256, 256>>>(xre, xim);
    wsplit_kernel<<<(KC_ * (KC_/4)) / 256, 256>>>(Wq_re, Wq_im, 0);
    wsplit_kernel<<<(KC_ * (KC_/4)) / 256, 256>>>(Wk_re, Wk_im, 1);
    wsplit_kernel<<<(D_  * (KC_/4)) / 256, 256>>>(Wv_re, Wv_im, 2);

    // merged Q/K/V projections: 512 + 512 + 256 tiles
    gemm_mma_kernel<<<1280, 256>>>(0, bq_re, bq_im, bk_re, bk_im, bv_re, nullptr);

    vtrans_kernel<<<dim3(D_/32, S_/32, B_), dim3(32, 8)>>>();

    // scores: 128x128 tiles, (16,16,4)
    gemm_mma_kernel<<<dim3(S_/128, S_/128, B_), 256>>>(
        1, nullptr, nullptr, nullptr, nullptr, nullptr, nullptr);

    softmax_kernel<<<B_*S_, 256>>>();

    // AV: (4,16,4)
    gemm_mma_kernel<<<dim3(D_/128, S_/128, B_), 256>>>(
        2, nullptr, nullptr, nullptr, nullptr, nullptr, (float*)d_out);
}

// round 15
// speedup vs baseline: 2.4357x; 1.2056x over previous
#include <cuda_runtime.h>
#include <cuda_bf16.h>
#include <cstdint>

#define D_ 512
#define S_ 2048
#define B_ 4
#define M_ (B_*S_)
#define KC_ 1024   // concat(re,im) contraction length

// ---- scratch (device globals; no allocation allowed) ----
__device__ __align__(16) float g_Vre[M_*D_];
__device__ __align__(16) float g_S[(size_t)B_*S_*S_];
__device__ __align__(16) __nv_bfloat16 g_Qhi[(size_t)M_*KC_], g_Qlo[(size_t)M_*KC_];
__device__ __align__(16) __nv_bfloat16 g_Khi[(size_t)M_*KC_], g_Klo[(size_t)M_*KC_];
__device__ __align__(16) __nv_bfloat16 g_Xhi[(size_t)M_*KC_], g_Xlo[(size_t)M_*KC_];
__device__ __align__(16) __nv_bfloat16 g_WBhi[3][(size_t)KC_*KC_], g_WBlo[3][(size_t)KC_*KC_];
__device__ __align__(16) __nv_bfloat16 g_Phi[(size_t)B_*S_*S_], g_Plo[(size_t)B_*S_*S_];
__device__ __align__(16) __nv_bfloat16 g_Vthi[(size_t)B_*D_*S_], g_Vtlo[(size_t)B_*D_*S_];

// =====================================================================
// helpers
// =====================================================================
static __device__ __forceinline__ uint32_t smem_u32(const void* p) {
    uint32_t a;
    asm("{ .reg .u64 t; cvta.to.shared.u64 t, %1; cvt.u32.u64 %0, t; }"
        : "=r"(a) : "l"(p));
    return a;
}
static __device__ __forceinline__ void ldsm_x4(uint32_t addr, uint32_t& r0,
                                               uint32_t& r1, uint32_t& r2, uint32_t& r3) {
    asm volatile("ldmatrix.sync.aligned.m8n8.x4.shared.b16 {%0,%1,%2,%3}, [%4];"
                 : "=r"(r0), "=r"(r1), "=r"(r2), "=r"(r3) : "r"(addr));
}
static __device__ __forceinline__ void mma_bf16(float* d, const uint32_t* a,
                                                const uint32_t* b) {
    asm volatile("mma.sync.aligned.m16n8k16.row.col.f32.bf16.bf16.f32 "
                 "{%0,%1,%2,%3}, {%4,%5,%6,%7}, {%8,%9}, {%0,%1,%2,%3};"
                 : "+f"(d[0]), "+f"(d[1]), "+f"(d[2]), "+f"(d[3])
                 : "r"(a[0]), "r"(a[1]), "r"(a[2]), "r"(a[3]),
                   "r"(b[0]), "r"(b[1]));
}
#define CP_ASYNC16(sa, gp) \
    asm volatile("cp.async.cg.shared.global [%0], [%1], 16;" :: "r"(sa), "l"(gp))
#define CP_COMMIT()  asm volatile("cp.async.commit_group;" ::: "memory")
#define CP_WAIT_1()  asm volatile("cp.async.wait_group 1;" ::: "memory")
#define CP_WAIT_0()  asm volatile("cp.async.wait_group 0;" ::: "memory")

static __device__ __forceinline__ void split_store4(
    __nv_bfloat16* hi, __nv_bfloat16* lo, size_t off, float4 v) {
    __nv_bfloat16 h0 = __float2bfloat16_rn(v.x), h1 = __float2bfloat16_rn(v.y);
    __nv_bfloat16 h2 = __float2bfloat16_rn(v.z), h3 = __float2bfloat16_rn(v.w);
    *(__nv_bfloat162*)(hi + off)     = __nv_bfloat162(h0, h1);
    *(__nv_bfloat162*)(hi + off + 2) = __nv_bfloat162(h2, h3);
    *(__nv_bfloat162*)(lo + off)     = __nv_bfloat162(
        __float2bfloat16_rn(v.x - __bfloat162float(h0)),
        __float2bfloat16_rn(v.y - __bfloat162float(h1)));
    *(__nv_bfloat162*)(lo + off + 2) = __nv_bfloat162(
        __float2bfloat16_rn(v.z - __bfloat162float(h2)),
        __float2bfloat16_rn(v.w - __bfloat162float(h3)));
}
static __device__ __forceinline__ void split_store2(
    __nv_bfloat16* hi, __nv_bfloat16* lo, size_t off, float v0, float v1) {
    __nv_bfloat16 h0 = __float2bfloat16_rn(v0), h1 = __float2bfloat16_rn(v1);
    *(__nv_bfloat162*)(hi + off) = __nv_bfloat162(h0, h1);
    *(__nv_bfloat162*)(lo + off) = __nv_bfloat162(
        __float2bfloat16_rn(v0 - __bfloat162float(h0)),
        __float2bfloat16_rn(v1 - __bfloat162float(h1)));
}
// Fast exp on the FMA pipe (degree-5 poly); x <= 0 expected.
static __device__ __forceinline__ float fexp(float x) {
    x = fmaxf(x, -87.0f);
    const float n = rintf(x * 1.44269504f);
    const float r = fmaf(n, -0.693359375f, x) - n * -2.12194440e-4f;
    float p = 1.9875691500e-4f;
    p = fmaf(p, r, 1.3981999507e-3f);
    p = fmaf(p, r, 8.3334519073e-3f);
    p = fmaf(p, r, 4.1665795894e-2f);
    p = fmaf(p, r, 1.6666665459e-1f);
    p = fmaf(p, r, 5.0000001201e-1f);
    p = fmaf(p * r, r, r) + 1.0f;
    const int e = ((int)n + 127) << 23;
    return p * __int_as_float(e);
}

// =====================================================================
// Fused converts: blocks [0,8192) = xsplit; [8192,9216) Wq; [9216,10240) Wk;
// [10240,10752) Wv(real rows only).
// =====================================================================
__global__ __launch_bounds__(256) void convert_all_kernel(
    const float* __restrict__ xre, const float* __restrict__ xim,
    const float* __restrict__ Wqre, const float* __restrict__ Wqim,
    const float* __restrict__ Wkre, const float* __restrict__ Wkim,
    const float* __restrict__ Wvre, const float* __restrict__ Wvim)
{
    const int bb = blockIdx.x;
    if (bb < 8192) {
        const size_t idx = (size_t)bb * 256 + threadIdx.x;
        const size_t row = idx >> 8;
        const int c4 = (int)(idx & 255) * 4;
        const size_t soff = row * D_ + ((c4 < D_) ? c4 : c4 - D_);
        const float4 v = (c4 < D_) ? *(const float4*)(xre + soff)
                                   : *(const float4*)(xim + soff);
        split_store4(g_Xhi, g_Xlo, row * KC_ + c4, v);
        return;
    }
    int w; const float *Wre, *Wim; int base;
    if (bb < 9216)       { w = 0; Wre = Wqre; Wim = Wqim; base = 8192; }
    else if (bb < 10240) { w = 1; Wre = Wkre; Wim = Wkim; base = 9216; }
    else                 { w = 2; Wre = Wvre; Wim = Wvim; base = 10240; }
    const size_t idx = (size_t)(bb - base) * 256 + threadIdx.x;
    const int n = (int)(idx >> 8);
    const int c4 = (int)(idx & 255) * 4;
    float4 v;
    if (n < D_) {
        if (c4 < D_) v = *(const float4*)(Wre + (size_t)n * D_ + c4);
        else {
            v = *(const float4*)(Wim + (size_t)n * D_ + c4 - D_);
            v.x = -v.x; v.y = -v.y; v.z = -v.z; v.w = -v.w;
        }
    } else {
        if (c4 < D_) v = *(const float4*)(Wim + (size_t)(n - D_) * D_ + c4);
        else         v = *(const float4*)(Wre + (size_t)(n - D_) * D_ + c4 - D_);
    }
    split_store4(g_WBhi[w], g_WBlo[w], (size_t)n * KC_ + c4, v);
}

__global__ void vtrans_kernel()
{
    __shared__ float sm[32][33];
    const int b = blockIdx.z;
    const int e0 = blockIdx.x * 32, t0 = blockIdx.y * 32;
    const int tx = threadIdx.x, ty = threadIdx.y;  // 32 x 8
    const float* src = g_Vre + (size_t)b * S_ * D_;
#pragma unroll
    for (int i = 0; i < 4; i++)
        sm[ty + i*8][tx] = src[(size_t)(t0 + ty + i*8) * D_ + e0 + tx];
    __syncthreads();
    const size_t dbase = (size_t)b * D_ * S_;
#pragma unroll
    for (int i = 0; i < 4; i++) {
        const int e = e0 + ty + i*8, t = t0 + tx;
        const float v = sm[tx][ty + i*8];
        const __nv_bfloat16 h = __float2bfloat16_rn(v);
        g_Vthi[dbase + (size_t)e * S_ + t] = h;
        g_Vtlo[dbase + (size_t)e * S_ + t] =
            __float2bfloat16_rn(v - __bfloat162float(h));
    }
}

// =====================================================================
// Unified mma GEMM, CTA 128x128, 8 warps (4x2), warp tile 32x64,
// cp.async 3-stage pipeline (one __syncthreads per 32-K chunk).
// kind 0: merged proj; kind 1: scores; kind 2: AV. 3-pass split-2.
// =====================================================================
__global__ __launch_bounds__(256) void gemm_mma_kernel(
    int kind,
    const float* __restrict__ bqre, const float* __restrict__ bqim,
    const float* __restrict__ bkre, const float* __restrict__ bkim,
    const float* __restrict__ bvre,
    float* __restrict__ outp)
{
    __shared__ __align__(128) uint8_t smA[3][8192];
    __shared__ __align__(128) uint8_t smB[3][8192];

    const int tid = threadIdx.x;
    const int wid = tid >> 5, lid = tid & 31;
    const int wm = wid >> 1, wn = wid & 1;

    int mode, m0, n0, z = 0;
    if (kind == 0) {
        int t = blockIdx.x;
        if (t < 512)       { mode = 0; m0 = (t >> 3) * 128; n0 = (t & 7) * 128; }
        else if (t < 1024) { t -= 512;  mode = 1; m0 = (t >> 3) * 128; n0 = (t & 7) * 128; }
        else               { t -= 1024; mode = 2; m0 = (t >> 2) * 128; n0 = (t & 3) * 128; }
    } else if (kind == 1) {
        mode = 4; m0 = blockIdx.y * 128; n0 = blockIdx.x * 128; z = blockIdx.z;
    } else {
        mode = 3; m0 = blockIdx.y * 128; n0 = blockIdx.x * 128; z = blockIdx.z;
    }

    const __nv_bfloat16 *A0, *A1, *A2, *B0, *B1, *B2;
    int lda, Kpass;
    size_t abase = 0, bbase = 0;
    if (mode <= 2) {
        A0 = g_Xhi; A1 = g_Xlo; A2 = g_Xhi;
        B0 = g_WBhi[mode]; B1 = g_WBhi[mode]; B2 = g_WBlo[mode];
        lda = KC_; Kpass = KC_;
    } else if (mode == 3) {
        A0 = g_Phi; A1 = g_Plo; A2 = g_Phi;
        B0 = g_Vthi; B1 = g_Vthi; B2 = g_Vtlo;
        lda = S_; Kpass = S_;
        abase = (size_t)z * S_ * S_;
        bbase = (size_t)z * D_ * S_;
    } else {
        A0 = g_Qhi; A1 = g_Qlo; A2 = g_Qhi;
        B0 = g_Khi; B1 = g_Khi; B2 = g_Klo;
        lda = KC_; Kpass = KC_;
        abase = (size_t)z * S_ * KC_;
        bbase = (size_t)z * S_ * KC_;
    }
    const int KCH = Kpass / 32;       // chunks per pass
    const int NIT = 3 * KCH;

    const int grow = tid >> 1;
    const int gc0  = (tid & 1) * 2;
    const size_t aoff = abase + (size_t)(m0 + grow) * lda;
    const size_t boff = bbase + (size_t)(n0 + grow) * lda;

    const int spr = grow >> 1, sh = grow & 1;
    uint32_t st_off[2];
#pragma unroll
    for (int q = 0; q < 2; q++) {
        int pos = sh * 4 + gc0 + q;
        st_off[q] = (uint32_t)(spr * 128 + (pos ^ (spr & 7)) * 16);
    }

    uint32_t offA[2][2];
#pragma unroll
    for (int mt = 0; mt < 2; mt++)
#pragma unroll
        for (int ks = 0; ks < 2; ks++) {
            int r = wm * 32 + mt * 16 + (lid & 15);
            int c16 = ks * 2 + (lid >> 4);
            int pr = r >> 1, hh = r & 1;
            int pos = hh * 4 + c16;
            offA[mt][ks] = (uint32_t)(pr * 128 + (pos ^ (pr & 7)) * 16);
        }
    uint32_t offB[4][2];
#pragma unroll
    for (int ntp = 0; ntp < 4; ntp++)
#pragma unroll
        for (int ks = 0; ks < 2; ks++) {
            int rn = wn * 64 + ntp * 16 + (lid & 7) + ((lid >> 4) & 1) * 8;
            int c16 = ks * 2 + ((lid >> 3) & 1);
            int pr = rn >> 1, hh = rn & 1;
            int pos = hh * 4 + c16;
            offB[ntp][ks] = (uint32_t)(pr * 128 + (pos ^ (pr & 7)) * 16);
        }

    float acc[2][8][4];
#pragma unroll
    for (int mt = 0; mt < 2; mt++)
#pragma unroll
        for (int nt = 0; nt < 8; nt++)
#pragma unroll
            for (int i = 0; i < 4; i++) acc[mt][nt][i] = 0.f;

    uint32_t aS[3], bS[3];
#pragma unroll
    for (int s = 0; s < 3; s++) {
        aS[s] = smem_u32(&smA[s][0]);
        bS[s] = smem_u32(&smB[s][0]);
    }

    // issue cp.async loads for chunk cc into stage buffer s
    auto issue = [&](int cc, int s) {
        const int pp = cc / KCH;
        const int kk = (cc - pp * KCH) * 32;
        const __nv_bfloat16* A  = (pp == 0) ? A0 : (pp == 1) ? A1 : A2;
        const __nv_bfloat16* Bq = (pp == 0) ? B0 : (pp == 1) ? B1 : B2;
#pragma unroll
        for (int q = 0; q < 2; q++) {
            CP_ASYNC16(aS[s] + st_off[q], A  + aoff + kk + (gc0 + q) * 8);
            CP_ASYNC16(bS[s] + st_off[q], Bq + boff + kk + (gc0 + q) * 8);
        }
    };

    issue(0, 0); CP_COMMIT();
    issue(1, 1); CP_COMMIT();

    int stage = 0;
    for (int c = 0; c < NIT; c++) {
        if (c + 1 < NIT) { CP_WAIT_1(); } else { CP_WAIT_0(); }
        __syncthreads();               // stage(c) visible; all MMA(c-1) done
        if (c + 2 < NIT) {             // prefetch into the buffer freed at c-1
            int s2 = stage + 2; if (s2 >= 3) s2 -= 3;
            issue(c + 2, s2);
            CP_COMMIT();
        }
        const uint32_t aBase = aS[stage];
        const uint32_t bBase = bS[stage];
#pragma unroll
        for (int ks = 0; ks < 2; ks++) {
            uint32_t af[2][4];
            ldsm_x4(aBase + offA[0][ks], af[0][0], af[0][1], af[0][2], af[0][3]);
            ldsm_x4(aBase + offA[1][ks], af[1][0], af[1][1], af[1][2], af[1][3]);
            uint32_t bf[8][2];
#pragma unroll
            for (int ntp = 0; ntp < 4; ntp++)
                ldsm_x4(bBase + offB[ntp][ks],
                        bf[2*ntp][0], bf[2*ntp][1], bf[2*ntp+1][0], bf[2*ntp+1][1]);
#pragma unroll
            for (int mt = 0; mt < 2; mt++)
#pragma unroll
                for (int nt = 0; nt < 8; nt++)
                    mma_bf16(acc[mt][nt], af[mt], bf[nt]);
        }
        if (++stage == 3) stage = 0;
    }

    // ---- epilogue ----
    if (mode <= 1) {
        __nv_bfloat16* ph = (mode == 0) ? g_Qhi : g_Khi;
        __nv_bfloat16* pl = (mode == 0) ? g_Qlo : g_Klo;
        const float* bre = (mode == 0) ? bqre : bkre;
        const float* bim = (mode == 0) ? bqim : bkim;
#pragma unroll
        for (int mt = 0; mt < 2; mt++) {
            const int row = m0 + wm * 32 + mt * 16 + (lid >> 2);
#pragma unroll
            for (int nt = 0; nt < 8; nt++) {
                const int col = n0 + wn * 64 + nt * 8 + (lid & 3) * 2;
                const float b0 = (col < D_) ? bre[col]     : bim[col - D_];
                const float b1 = (col < D_) ? bre[col + 1] : bim[col - D_ + 1];
                split_store2(ph, pl, (size_t)row * KC_ + col,
                             acc[mt][nt][0] + b0, acc[mt][nt][1] + b1);
                split_store2(ph, pl, (size_t)(row + 8) * KC_ + col,
                             acc[mt][nt][2] + b0, acc[mt][nt][3] + b1);
            }
        }
    } else if (mode == 2) {
#pragma unroll
        for (int mt = 0; mt < 2; mt++) {
            const int row = m0 + wm * 32 + mt * 16 + (lid >> 2);
#pragma unroll
            for (int nt = 0; nt < 8; nt++) {
                const int col = n0 + wn * 64 + nt * 8 + (lid & 3) * 2;
                const float b0 = bvre[col], b1 = bvre[col + 1];
                *(float2*)(g_Vre + (size_t)row * D_ + col) =
                    make_float2(acc[mt][nt][0] + b0, acc[mt][nt][1] + b1);
                *(float2*)(g_Vre + (size_t)(row + 8) * D_ + col) =
                    make_float2(acc[mt][nt][2] + b0, acc[mt][nt][3] + b1);
            }
        }
    } else if (mode == 3) {
#pragma unroll
        for (int mt = 0; mt < 2; mt++) {
            const int row = m0 + wm * 32 + mt * 16 + (lid >> 2);
            float* o = outp + ((size_t)z * S_ + row) * D_;
#pragma unroll
            for (int nt = 0; nt < 8; nt++) {
                const int col = n0 + wn * 64 + nt * 8 + (lid & 3) * 2;
                *(float2*)(o + col)          = make_float2(acc[mt][nt][0], acc[mt][nt][1]);
                *(float2*)(o + 8 * D_ + col) = make_float2(acc[mt][nt][2], acc[mt][nt][3]);
            }
        }
    } else {
#pragma unroll
        for (int mt = 0; mt < 2; mt++) {
            const int row = m0 + wm * 32 + mt * 16 + (lid >> 2);
            float* Sr = g_S + ((size_t)z * S_ + row) * S_;
#pragma unroll
            for (int nt = 0; nt < 8; nt++) {
                const int col = n0 + wn * 64 + nt * 8 + (lid & 3) * 2;
                *(float2*)(Sr + col)          = make_float2(acc[mt][nt][0], acc[mt][nt][1]);
                *(float2*)(Sr + 8 * S_ + col) = make_float2(acc[mt][nt][2], acc[mt][nt][3]);
            }
        }
    }
}

// =====================================================================
// Row softmax; poly exp (FMA pipe); writes split-bf16 P.
// =====================================================================
__global__ __launch_bounds__(256) void softmax_kernel()
{
    __shared__ float sh[8];
    const size_t row = blockIdx.x;
    const float* p = g_S + row * S_;
    const int t = threadIdx.x;

    float4 v0 = *(const float4*)(p + t*4);
    float4 v1 = *(const float4*)(p + 1024 + t*4);

    float m = fmaxf(fmaxf(fmaxf(v0.x, v0.y), fmaxf(v0.z, v0.w)),
                    fmaxf(fmaxf(v1.x, v1.y), fmaxf(v1.z, v1.w)));
#pragma unroll
    for (int o = 16; o; o >>= 1) m = fmaxf(m, __shfl_xor_sync(0xffffffffu, m, o));
    if ((t & 31) == 0) sh[t >> 5] = m;
    __syncthreads();
    m = sh[0];
#pragma unroll
    for (int i = 1; i < 8; i++) m = fmaxf(m, sh[i]);
    __syncthreads();

    v0.x = fexp(v0.x - m); v0.y = fexp(v0.y - m);
    v0.z = fexp(v0.z - m); v0.w = fexp(v0.w - m);
    v1.x = fexp(v1.x - m); v1.y = fexp(v1.y - m);
    v1.z = fexp(v1.z - m); v1.w = fexp(v1.w - m);

    float s = (v0.x + v0.y) + (v0.z + v0.w) + (v1.x + v1.y) + (v1.z + v1.w);
#pragma unroll
    for (int o = 16; o; o >>= 1) s += __shfl_xor_sync(0xffffffffu, s, o);
    if ((t & 31) == 0) sh[t >> 5] = s;
    __syncthreads();
    s = (sh[0] + sh[1]) + (sh[2] + sh[3]) + (sh[4] + sh[5]) + (sh[6] + sh[7]);
    const float inv = 1.0f / s;

    v0.x *= inv; v0.y *= inv; v0.z *= inv; v0.w *= inv;
    v1.x *= inv; v1.y *= inv; v1.z *= inv; v1.w *= inv;
    split_store4(g_Phi, g_Plo, row * S_ + t*4, v0);
    split_store4(g_Phi, g_Plo, row * S_ + 1024 + t*4, v1);
}

// =====================================================================
extern "C" void kernel_launch(void* const* d_in, const int* in_sizes, int n_in,
                              void* d_out, int out_size)
{
    (void)in_sizes; (void)n_in; (void)out_size;

    const float* xre   = (const float*)d_in[0];
    const float* xim   = (const float*)d_in[1];
    const float* Wq_re = (const float*)d_in[2];
    const float* Wq_im = (const float*)d_in[3];
    const float* bq_re = (const float*)d_in[4];
    const float* bq_im = (const float*)d_in[5];
    const float* Wk_re = (const float*)d_in[6];
    const float* Wk_im = (const float*)d_in[7];
    const float* bk_re = (const float*)d_in[8];
    const float* bk_im = (const float*)d_in[9];
    const float* Wv_re = (const float*)d_in[10];
    const float* Wv_im = (const float*)d_in[11];
    const float* bv_re = (const float*)d_in[12];

    // fused converts: x + Wq + Wk + Wv
    convert_all_kernel<<<10752, 256>>>(xre, xim, Wq_re, Wq_im,
                                       Wk_re, Wk_im, Wv_re, Wv_im);

    // merged Q/K/V projections: 512 + 512 + 256 tiles
    gemm_mma_kernel<<<1280, 256>>>(0, bq_re, bq_im, bk_re, bk_im, bv_re, nullptr);

    vtrans_kernel<<<dim3(D_/32, S_/32, B_), dim3(32, 8)>>>();

    // scores: (16,16,4)
    gemm_mma_kernel<<<dim3(S_/128, S_/128, B_), 256>>>(
        1, nullptr, nullptr, nullptr, nullptr, nullptr, nullptr);

    softmax_kernel<<<B_*S_, 256>>>();

    // AV: (4,16,4)
    gemm_mma_kernel<<<dim3(D_/128, S_/128, B_), 256>>>(
        2, nullptr, nullptr, nullptr, nullptr, nullptr, (float*)d_out);
}